// round 12
// baseline (speedup 1.0000x reference)
#include <cuda_runtime.h>
#include <cuda_fp16.h>
#include <math.h>
#include <stdint.h>

#define B_TOTAL 131072
#define DIM     128
#define HID     256
#define NB      8
#define NL      4
#define KSEL    2
#define FIN     32
#define ROWS    128
#define LDH     132          // s_h float stride
#define TLW     68           // hn fp16 tile stride in 32-bit words (128 cols)
#define TLT     132          // t  fp16 tile stride in 32-bit words (256 cols)
#define THREADS 512

typedef unsigned long long u64;

__device__ int   g_sel[NL * KSEL];
__device__ float g_gfac[NL * KSEL][DIM];
__device__ float g_b2f[NL * KSEL][DIM];     // 0.5 * b2 * gfac
// fp16 tensor stream: 32 chunks x 24KB  [ks(8)][jp(6)][t(4)][nl(8)][k2(4)]
__device__ __align__(256) uint4 g_wpack[49152];
// fp32 FFMA stream: 8 slots x 16384 floats (G1 [k 128][ci 64] + G2 [k 256][ci 32])
__device__ __align__(256) float g_wf[131072];

__device__ __forceinline__ float sigm(float x) { return 1.0f / (1.0f + expf(-x)); }
__device__ __forceinline__ float gelu_exact(float x) {
    return 0.5f * x * (1.0f + erff(x * 0.70710678118654752440f));
}
// Branchless GELU (A&S 7.1.26, abs err 1.5e-7; validated R9/R10)
__device__ __forceinline__ float gelu_fast(float x) {
    float u = fabsf(x) * 0.70710678118654752440f;
    float t = __fdividef(1.0f, fmaf(0.3275911f, u, 1.0f));
    float p = t * fmaf(t, fmaf(t, fmaf(t, fmaf(t, 1.061405429f, -1.453152027f),
                                       1.421413741f), -0.284496736f), 0.254829592f);
    float erfc_abs = p * __expf(-u * u);
    float er = copysignf(1.0f - erfc_abs, x);
    return 0.5f * x * (1.0f + er);
}
__device__ __forceinline__ uint32_t pkh2(float x, float y) {
    return (uint32_t)__half_as_ushort(__float2half_rn(x))
         | ((uint32_t)__half_as_ushort(__float2half_rn(y)) << 16);
}
__device__ __forceinline__ uint32_t pkf2(float lo, float hi) {
    uint32_t r;
    asm("cvt.rn.f16x2.f32 %0, %1, %2;" : "=r"(r) : "f"(hi), "f"(lo));
    return r;
}
__device__ __forceinline__ void cp16(uint32_t d, const void* s) {
    asm volatile("cp.async.cg.shared.global [%0], [%1], 16;" :: "r"(d), "l"(s));
}
__device__ __forceinline__ void mma_fp16(float c[4], uint32_t a0, uint32_t a1,
                                         uint32_t a2, uint32_t a3,
                                         uint32_t b0, uint32_t b1) {
    asm volatile("mma.sync.aligned.m16n8k16.row.col.f32.f16.f16.f32 "
        "{%0,%1,%2,%3},{%4,%5,%6,%7},{%8,%9},{%0,%1,%2,%3};"
        : "+f"(c[0]), "+f"(c[1]), "+f"(c[2]), "+f"(c[3])
        : "r"(a0), "r"(a1), "r"(a2), "r"(a3), "r"(b0), "r"(b1));
}
__device__ __forceinline__ void ldsm4(uint32_t r[4], uint32_t addr) {
    asm volatile("ldmatrix.sync.aligned.m8n8.x4.shared.b16 {%0,%1,%2,%3}, [%4];"
        : "=r"(r[0]), "=r"(r[1]), "=r"(r[2]), "=r"(r[3]) : "r"(addr));
}
__device__ __forceinline__ u64 ffma2v(u64 a, u64 b, u64 c) {
    u64 d; asm("fma.rn.f32x2 %0, %1, %2, %3;" : "=l"(d) : "l"(a), "l"(b), "l"(c)); return d;
}
__device__ __forceinline__ u64 pkaa(float a) {
    u64 r; asm("mov.b64 %0, {%1, %1};" : "=l"(r) : "f"(a)); return r;
}
__device__ __forceinline__ float2 unpk(u64 v) {
    float2 r; asm("mov.b64 {%0, %1}, %2;" : "=f"(r.x), "=f"(r.y) : "l"(v)); return r;
}

// ---------------------------------------------------------------------------
// Pilot (R11-proven): sample-0 trajectory, params prefetched to smem
// ---------------------------------------------------------------------------
__global__ void __launch_bounds__(1024, 1)
pilot_kernel(const float* __restrict__ x, const float* __restrict__ pw,
             const float* __restrict__ pb, const float* __restrict__ pos,
             const float* __restrict__ sel_w, const float* __restrict__ sel_b,
             const float* __restrict__ ln_s, const float* __restrict__ ln_b,
             const float* __restrict__ w1, const float* __restrict__ b1,
             const float* __restrict__ w2, const float* __restrict__ b2,
             const float* __restrict__ gate, const float* __restrict__ tf) {
    extern __shared__ float ps[];
    float* s_selw = ps;             // 4096
    float* s_lns  = ps + 4096;      // 4096
    float* s_lnb  = ps + 8192;      // 4096
    float* s_b1a  = ps + 12288;     // 8192
    float* s_b2a  = ps + 20480;     // 4096
    float* s_gate = ps + 24576;     // 4096
    float* s_tf   = ps + 28672;     // 128
    float* s_selb = ps + 28800;     // 32

    __shared__ float h0[DIM], hn[DIM], tbuf[HID], fbuf[DIM];
    __shared__ float part[8][256];
    __shared__ float redA[64], redB[64];
    __shared__ float sc[NB];
    __shared__ int   seli[KSEL];
    __shared__ float s_mu, s_rstd;
    int tid = threadIdx.x, lane = tid & 31, wid = tid >> 5;

    {
        ((float4*)s_selw)[tid & 1023] = ((const float4*)sel_w)[tid & 1023];
        ((float4*)s_lns)[tid & 1023]  = ((const float4*)ln_s)[tid & 1023];
        ((float4*)s_lnb)[tid & 1023]  = ((const float4*)ln_b)[tid & 1023];
        ((float4*)s_b1a)[tid]         = ((const float4*)b1)[tid];
        ((float4*)s_b1a)[tid + 1024]  = ((const float4*)b1)[tid + 1024];
        ((float4*)s_b2a)[tid & 1023]  = ((const float4*)b2)[tid & 1023];
        ((float4*)s_gate)[tid & 1023] = ((const float4*)gate)[tid & 1023];
        if (tid < 32) ((float4*)s_tf)[tid] = ((const float4*)tf)[tid];
        else if (tid < 40) ((float4*)s_selb)[tid - 32] = ((const float4*)sel_b)[tid - 32];
    }

    if (tid < DIM) {
        float acc = pb[tid] + pos[tid];
#pragma unroll
        for (int k = 0; k < FIN; k++) acc += x[k] * pw[k * DIM + tid];
        h0[tid] = acc;
    }
    __syncthreads();

    for (int l = 0; l < NL; l++) {
        {
            int b = tid >> 7, d = tid & 127;
            float pv = h0[d] * s_selw[(l * DIM + d) * NB + b];
#pragma unroll
            for (int o = 16; o > 0; o >>= 1) pv += __shfl_xor_sync(0xffffffffu, pv, o);
            if (lane == 0) part[0][wid] = pv;
        }
        __syncthreads();
        if (tid < NB) {
            float s = part[0][tid * 4] + part[0][tid * 4 + 1]
                    + part[0][tid * 4 + 2] + part[0][tid * 4 + 3];
            sc[tid] = sigm(s + s_selb[l * NB + tid]) * 0.6f + 0.2f;
        }
        __syncthreads();
        if (tid == 0) {
            int i0 = 0; float v0 = -1e30f;
            for (int j = 0; j < NB; j++) if (sc[j] > v0) { v0 = sc[j]; i0 = j; }
            int i1 = -1; float v1 = -1e30f;
            for (int j = 0; j < NB; j++) { if (j == i0) continue; if (sc[j] > v1) { v1 = sc[j]; i1 = j; } }
            seli[0] = i0; seli[1] = i1;
            g_sel[l * KSEL + 0] = i0; g_sel[l * KSEL + 1] = i1;
        }
        __syncthreads();

        for (int k = 0; k < KSEL; k++) {
            int i = seli[k];
            int bo = l * NB + i;
            if (tid < DIM) {
                float fv = 1.0f + sigm(s_gate[bo * DIM + tid]) * s_tf[tid];
                fbuf[tid] = fv;
                g_gfac[l * KSEL + k][tid] = fv;
                g_b2f[l * KSEL + k][tid] = 0.5f * s_b2a[bo * DIM + tid] * fv;
            }
            if (tid < 64) {
                float a = h0[tid], b = h0[tid + 64];
                redA[tid] = a + b; redB[tid] = a * a + b * b;
            }
            __syncthreads();
            if (tid == 0) {
                float s = 0.f, q = 0.f;
                for (int j = 0; j < 64; j++) { s += redA[j]; q += redB[j]; }
                float mu = s * (1.0f / DIM);
                s_mu = mu;
                s_rstd = rsqrtf(q * (1.0f / DIM) - mu * mu + 1e-5f);
            }
            __syncthreads();
            if (tid < DIM)
                hn[tid] = (h0[tid] - s_mu) * s_rstd * s_lns[bo * DIM + tid] + s_lnb[bo * DIM + tid];
            __syncthreads();
            {
                int col = tid & 255, seg = tid >> 8, k0 = seg * 32;
                const float* W1 = w1 + (size_t)bo * DIM * HID;
                float acc = 0.f;
#pragma unroll
                for (int kk = 0; kk < 32; kk++)
                    acc += hn[k0 + kk] * __ldg(&W1[(size_t)(k0 + kk) * HID + col]);
                part[seg][col] = acc;
            }
            __syncthreads();
            if (tid < HID)
                tbuf[tid] = gelu_exact(part[0][tid] + part[1][tid] + part[2][tid] + part[3][tid]
                                       + s_b1a[bo * HID + tid]);
            __syncthreads();
            {
                int col = tid & 127, seg = tid >> 7, k0 = seg * 32;
                const float* W2 = w2 + (size_t)bo * HID * DIM;
                float acc = 0.f;
#pragma unroll
                for (int kk = 0; kk < 32; kk++)
                    acc += tbuf[k0 + kk] * __ldg(&W2[(size_t)(k0 + kk) * DIM + col]);
                part[seg][col] = acc;
            }
            __syncthreads();
            if (tid < DIM) {
                float z = part[0][tid] + part[1][tid] + part[2][tid] + part[3][tid]
                        + part[4][tid] + part[5][tid] + part[6][tid] + part[7][tid]
                        + s_b2a[bo * DIM + tid];
                h0[tid] += 0.5f * z * fbuf[tid];
            }
            __syncthreads();
        }
    }
}

// ---------------------------------------------------------------------------
// Repack. Blocks 0..31: fp16 ldsm chunks (24KB, 6144 words each).
//   q = slot*4 + ph; ph0/1: W1 cols ph*96..+95, k 0..127
//                    ph2/3: W2 out-cols 0..95, k (ph-2)*128..+127 (scaled 0.5*gfac)
// Blocks 32..39: fp32 FFMA stream per slot:
//   G1 [k 0..127][ci 0..63] = W1[k][192+ci]; G2 [k 0..255][ci 0..31] = W2[k][96+ci]*0.5*gfac
// ---------------------------------------------------------------------------
__global__ void repack_kernel(const float* __restrict__ w1g, const float* __restrict__ w2g) {
    int blkid = blockIdx.x;
    if (blkid < 32) {
        int q = blkid;
        int slot = q >> 2, ph = q & 3;
        int blk = g_sel[slot];
        size_t bo = (size_t)((slot >> 1) * NB + blk);
        bool isG2 = (ph >= 2);
        const float* W = isG2 ? (w2g + bo * HID * DIM) : (w1g + bo * DIM * HID);
        int ld = isG2 ? DIM : HID;
        uint32_t* dst = (uint32_t*)g_wpack + (size_t)q * 6144;
        for (int e2 = threadIdx.x; e2 < 6144; e2 += 256) {
            int k2 = e2 & 3, nl = (e2 >> 2) & 7, t = (e2 >> 5) & 3;
            int gidx = e2 >> 7;
            int jp = gidx % 6, ks = gidx / 6;
            int j = jp * 2 + (t >> 1), kh = t & 1;
            int kl = ks * 16 + kh * 8 + k2 * 2;
            int k, n; float scl = 1.0f;
            if (!isG2) { k = kl; n = ph * 96 + j * 8 + nl; }
            else       { k = (ph - 2) * 128 + kl; n = j * 8 + nl;
                         scl = 0.5f * g_gfac[slot][n]; }
            dst[e2] = pkh2(W[(size_t)k * ld + n] * scl, W[(size_t)(k + 1) * ld + n] * scl);
        }
    } else {
        int slot = blkid - 32;
        int blk = g_sel[slot];
        size_t bo = (size_t)((slot >> 1) * NB + blk);
        const float* W1 = w1g + bo * DIM * HID;
        const float* W2 = w2g + bo * HID * DIM;
        float* dst = g_wf + (size_t)slot * 16384;
        for (int f = threadIdx.x; f < 16384; f += 256) {
            float v;
            if (f < 8192) {
                int k = f >> 6, ci = f & 63;
                v = W1[(size_t)k * HID + 192 + ci];
            } else {
                int f2 = f - 8192;
                int k = f2 >> 5, ci = f2 & 31;
                v = W2[(size_t)k * DIM + 96 + ci] * 0.5f * g_gfac[slot][96 + ci];
            }
            dst[f] = v;
        }
    }
}

// ---------------------------------------------------------------------------
// SMEM byte offsets
// ---------------------------------------------------------------------------
#define OFF_H    0                    // 128*132*4 = 67584
#define OFF_HN   67584                // 128*68*4  = 34816
#define OFF_T    102400               // 128*132*4 = 67584 (t holds all 256 cols)
#define OFF_WB   169984               // 2 x 24576 = 49152
#define OFF_B1   219136               // 1024
#define OFF_B2   220160               // 512
#define SMEM_TOT 220672

// ---------------------------------------------------------------------------
// Fused: proj -> 8 expert blocks (12 tensor warps + 4 FFMA warps) -> classifier
// ---------------------------------------------------------------------------
__global__ void __launch_bounds__(THREADS, 1)
fused_kernel(const float* __restrict__ xg, const float* __restrict__ pw,
             const float* __restrict__ pb, const float* __restrict__ pos,
             const float* __restrict__ b1g,
             const float* __restrict__ ln_s, const float* __restrict__ ln_b,
             const float* __restrict__ cls_w, const float* __restrict__ cls_b,
             float* __restrict__ out) {
    extern __shared__ char smem[];
    float*    s_h  = (float*)(smem + OFF_H);
    uint32_t* hn32 = (uint32_t*)(smem + OFF_HN);
    uint32_t* t32  = (uint32_t*)(smem + OFF_T);
    float*    s_b1 = (float*)(smem + OFF_B1);
    float*    s_b2 = (float*)(smem + OFF_B2);

    int tid = threadIdx.x, lane = tid & 31, wid = tid >> 5;
    int wm = wid & 3, wn = wid >> 2;          // wn 0..2 tensor, wn==3 -> FFMA warp
    bool is_ffma = (wn == 3);
    int g = lane >> 2, tg = lane & 3;
    size_t row0 = (size_t)blockIdx.x * ROWS;

    uint32_t base = (uint32_t)__cvta_generic_to_shared(smem);
    uint32_t hnb = base + OFF_HN;
    uint32_t tb  = base + OFF_T;
    uint32_t wb  = base + OFF_WB;

    // tensor ldsm offsets
    uint32_t aoffH = (uint32_t)(((wm * 32 + (lane & 15)) * TLW + (lane >> 4) * 4) * 4);
    uint32_t aoffT = (uint32_t)(((wm * 32 + (lane & 15)) * TLT + (lane >> 4) * 4) * 4);
    uint32_t boff  = (uint32_t)(wn * 1024 + lane * 16);
    // FFMA per-thread geometry
    int r0  = wm * 32 + (lane >> 3) * 8;      // 8 consecutive rows
    int ci0 = (lane & 7) * 8;                 // G1: 8 cols of 64-slice
    int ci0g = (lane & 7) * 4;                // G2: 4 cols of 32-slice

    // prefetch chunk 0 (24KB; 3 cp16/thread)
    {
        uint32_t d = wb + tid * 16;
        const char* s = (const char*)g_wpack + tid * 16;
        cp16(d, s); cp16(d + 8192, s + 8192); cp16(d + 16384, s + 16384);
        asm volatile("cp.async.commit_group;");
    }

    // ================= input projection =================
    {
        float* s_x  = (float*)(smem + OFF_HN);   // [128][36]
        float* s_pw = (float*)(smem + OFF_T);    // [32][132]
        for (int i = tid; i < 1024; i += THREADS) {
            int r = i >> 5, c4 = i & 31;
            *(float4*)&s_pw[r * LDH + c4 * 4] = *(const float4*)(pw + r * DIM + c4 * 4);
        }
        for (int i = tid; i < 1024; i += THREADS) {
            int r = i >> 3, c4 = i & 7;
            *(float4*)&s_x[r * 36 + c4 * 4] = *(const float4*)(xg + (row0 + r) * FIN + c4 * 4);
        }
        __syncthreads();
        int pr = tid >> 2, qt = tid & 3;
        int colb = qt * 32;
        float4 acc[8];
#pragma unroll
        for (int c4 = 0; c4 < 8; c4++) {
            int col = colb + c4 * 4;
            float4 a = *(const float4*)(pb + col);
            float4 po = *(const float4*)(pos + col);
            acc[c4].x = a.x + po.x; acc[c4].y = a.y + po.y;
            acc[c4].z = a.z + po.z; acc[c4].w = a.w + po.w;
        }
#pragma unroll 8
        for (int k = 0; k < FIN; k++) {
            float a = s_x[pr * 36 + k];
#pragma unroll
            for (int c4 = 0; c4 < 8; c4++) {
                float4 w = *(const float4*)&s_pw[k * LDH + colb + c4 * 4];
                acc[c4].x += a * w.x; acc[c4].y += a * w.y;
                acc[c4].z += a * w.z; acc[c4].w += a * w.w;
            }
        }
        __syncthreads();
#pragma unroll
        for (int c4 = 0; c4 < 8; c4++)
            *(float4*)&s_h[pr * LDH + colb + c4 * 4] = acc[c4];
        __syncthreads();
    }

    // ============================ 8 expert slots ============================
    for (int slot = 0; slot < NL * KSEL; slot++) {
        int blk = g_sel[slot];
        size_t bo = (size_t)((slot >> 1) * NB + blk);
        const float* LS = ln_s + bo * DIM;
        const float* LB = ln_b + bo * DIM;
        if (tid < HID) s_b1[tid] = __ldg(b1g + bo * HID + tid);
        else if (tid < HID + DIM) s_b2[tid - HID] = g_b2f[slot][tid - HID];

        // ---- LayerNorm -> hn32 (all 16 warps, rows wid*8..) ----
        {
            float4 ls4 = *(const float4*)(LS + lane * 4);
            float4 lb4 = *(const float4*)(LB + lane * 4);
#pragma unroll
            for (int rr = 0; rr < 8; rr++) {
                int r = wid * 8 + rr;
                float4 v = *(const float4*)&s_h[r * LDH + lane * 4];
                float s = v.x + v.y + v.z + v.w;
                float q = v.x * v.x + v.y * v.y + v.z * v.z + v.w * v.w;
#pragma unroll
                for (int o = 16; o > 0; o >>= 1) {
                    s += __shfl_xor_sync(0xffffffffu, s, o);
                    q += __shfl_xor_sync(0xffffffffu, q, o);
                }
                float mu = s * (1.0f / DIM);
                float rstd = rsqrtf(q * (1.0f / DIM) - mu * mu + 1e-5f);
                uint2 pk;
                pk.x = pkf2((v.x - mu) * rstd * ls4.x + lb4.x,
                            (v.y - mu) * rstd * ls4.y + lb4.y);
                pk.y = pkf2((v.z - mu) * rstd * ls4.z + lb4.z,
                            (v.w - mu) * rstd * ls4.w + lb4.w);
                *(uint2*)&hn32[r * TLW + lane * 2] = pk;
            }
        }

        float zacc[2][4][4];       // tensor G2 accumulators
        u64 acc1[8][4];            // FFMA G1 (8 rows x 4 col-pairs)
        u64 acc2g[8][2];           // FFMA G2 (8 rows x 2 col-pairs)
#pragma unroll
        for (int mt = 0; mt < 2; mt++)
#pragma unroll
            for (int j = 0; j < 4; j++)
#pragma unroll
                for (int e = 0; e < 4; e++) zacc[mt][j][e] = 0.0f;
#pragma unroll
        for (int ri = 0; ri < 8; ri++) {
#pragma unroll
            for (int c = 0; c < 4; c++) acc1[ri][c] = 0ULL;
            acc2g[ri][0] = 0ULL; acc2g[ri][1] = 0ULL;
        }

        for (int ph = 0; ph < 4; ph++) {
            int q = slot * 4 + ph;
            asm volatile("cp.async.wait_group 0;" ::: "memory");
            __syncthreads();
            {
                int nq = q + 1;
                if (nq < 32) {
                    uint32_t d = wb + (nq & 1) * 24576 + tid * 16;
                    const char* s = (const char*)g_wpack + (size_t)nq * 24576 + tid * 16;
                    cp16(d, s); cp16(d + 8192, s + 8192); cp16(d + 16384, s + 16384);
                }
                asm volatile("cp.async.commit_group;");
            }

            if (!is_ffma) {
                // ------------- tensor warps: 96 cols per phase -------------
                uint32_t wbc = wb + (q & 1) * 24576;
                bool isG1 = (ph < 2);
                uint32_t Ab = isG1 ? (hnb + aoffH)
                                   : (tb + aoffT + (ph == 3 ? 256u : 0u));
                uint32_t astr = isG1 ? (16 * TLW * 4) : (16 * TLT * 4);

                float c1[2][4][4];
                if (isG1) {
#pragma unroll
                    for (int mt = 0; mt < 2; mt++)
#pragma unroll
                        for (int j = 0; j < 4; j++)
#pragma unroll
                            for (int e = 0; e < 4; e++) c1[mt][j][e] = 0.0f;
                }
                float (*acc)[4][4] = isG1 ? c1 : zacc;

#pragma unroll
                for (int ks = 0; ks < 8; ks++) {
                    uint32_t b0[4], b1f[4];
                    ldsm4(b0,  wbc + boff + ks * 3072);
                    ldsm4(b1f, wbc + boff + ks * 3072 + 512);
                    uint32_t a0[4], a1[4];
                    ldsm4(a0, Ab + ks * 32);
                    ldsm4(a1, Ab + ks * 32 + astr);
#pragma unroll
                    for (int j = 0; j < 4; j++) {
                        uint32_t fb0 = (j < 2) ? b0[(j & 1) * 2]     : b1f[(j & 1) * 2];
                        uint32_t fb1 = (j < 2) ? b0[(j & 1) * 2 + 1] : b1f[(j & 1) * 2 + 1];
                        mma_fp16(acc[0][j], a0[0], a0[1], a0[2], a0[3], fb0, fb1);
                        mma_fp16(acc[1][j], a1[0], a1[1], a1[2], a1[3], fb0, fb1);
                    }
                }

                if (isG1) {
                    // GELU -> t32 words [ph*48 + wn*16 + j*4 + tg]
#pragma unroll
                    for (int mt = 0; mt < 2; mt++)
#pragma unroll
                        for (int j = 0; j < 4; j++) {
                            int colp = ph * 96 + wn * 32 + j * 8 + 2 * tg;
                            float bb0 = s_b1[colp];
                            float bb1 = s_b1[colp + 1];
                            int r = wm * 32 + mt * 16 + g;
                            int cw = ph * 48 + wn * 16 + j * 4 + tg;
                            t32[r * TLT + cw] =
                                pkf2(gelu_fast(c1[mt][j][0] + bb0), gelu_fast(c1[mt][j][1] + bb1));
                            t32[(r + 8) * TLT + cw] =
                                pkf2(gelu_fast(c1[mt][j][2] + bb0), gelu_fast(c1[mt][j][3] + bb1));
                        }
                }
            } else {
                // ------------- FFMA warp: fp32 slices on the fma pipe -------------
                if (ph < 2) {
                    // G1 slice cols 192..255, k window [ph*64, ph*64+64)
                    const float* WB1 = g_wf + (size_t)slot * 16384;
                    int kp0 = ph * 32, kp1 = kp0 + 32;
                    for (int kp = kp0; kp < kp1; kp++) {
                        const float* bp = WB1 + (2 * kp) * 64 + ci0;
                        ulonglong2 b00 = *(const ulonglong2*)(bp);
                        ulonglong2 b01 = *(const ulonglong2*)(bp + 4);
                        ulonglong2 b10 = *(const ulonglong2*)(bp + 64);
                        ulonglong2 b11 = *(const ulonglong2*)(bp + 68);
                        float alo[8], ahi[8];
#pragma unroll
                        for (int ri = 0; ri < 8; ri++) {
                            uint32_t w = hn32[(r0 + ri) * TLW + kp];
                            __half2 h2 = *(__half2*)&w;
                            float2 af = __half22float2(h2);
                            alo[ri] = af.x; ahi[ri] = af.y;
                        }
#pragma unroll
                        for (int ri = 0; ri < 8; ri++) {
                            u64 a = pkaa(alo[ri]);
                            acc1[ri][0] = ffma2v(a, b00.x, acc1[ri][0]);
                            acc1[ri][1] = ffma2v(a, b00.y, acc1[ri][1]);
                            acc1[ri][2] = ffma2v(a, b01.x, acc1[ri][2]);
                            acc1[ri][3] = ffma2v(a, b01.y, acc1[ri][3]);
                        }
#pragma unroll
                        for (int ri = 0; ri < 8; ri++) {
                            u64 a = pkaa(ahi[ri]);
                            acc1[ri][0] = ffma2v(a, b10.x, acc1[ri][0]);
                            acc1[ri][1] = ffma2v(a, b10.y, acc1[ri][1]);
                            acc1[ri][2] = ffma2v(a, b11.x, acc1[ri][2]);
                            acc1[ri][3] = ffma2v(a, b11.y, acc1[ri][3]);
                        }
                    }
                    if (ph == 1) {
                        // GELU + store t cols 192..255
#pragma unroll
                        for (int ri = 0; ri < 8; ri++) {
                            uint32_t w[4];
#pragma unroll
                            for (int cp = 0; cp < 4; cp++) {
                                float2 v = unpk(acc1[ri][cp]);
                                int col = 192 + ci0 + cp * 2;
                                w[cp] = pkf2(gelu_fast(v.x + s_b1[col]),
                                             gelu_fast(v.y + s_b1[col + 1]));
                            }
                            *(uint4*)&t32[(r0 + ri) * TLT + 96 + (ci0 >> 1)] =
                                make_uint4(w[0], w[1], w[2], w[3]);
                        }
                    }
                } else {
                    // G2 slice cols 96..127, kp window
                    const float* WB2 = g_wf + (size_t)slot * 16384 + 8192;
                    int kp0 = (ph - 2) * 64, kp1 = kp0 + 64;
                    for (int kp = kp0; kp < kp1; kp++) {
                        const float* bp = WB2 + (2 * kp) * 32 + ci0g;
                        ulonglong2 bk0 = *(const ulonglong2*)(bp);
                        ulonglong2 bk1 = *(const ulonglong2*)(bp + 32);
                        float alo[8], ahi[8];
#pragma unroll
                        for (int ri = 0; ri < 8; ri++) {
                            uint32_t w = t32[(r0 + ri) * TLT + kp];
                            __half2 h2 = *(__half2*)&w;
                            float2 af = __half22float2(h2);
                            alo[ri] = af.x; ahi[ri] = af.y;
                        }
#pragma unroll
                        for (int ri = 0; ri < 8; ri++) {
                            u64 a = pkaa(alo[ri]);
                            acc2g[ri][0] = ffma2v(a, bk0.x, acc2g[ri][0]);
                            acc2g[ri][1] = ffma2v(a, bk0.y, acc2g[ri][1]);
                        }
#pragma unroll
                        for (int ri = 0; ri < 8; ri++) {
                            u64 a = pkaa(ahi[ri]);
                            acc2g[ri][0] = ffma2v(a, bk1.x, acc2g[ri][0]);
                            acc2g[ri][1] = ffma2v(a, bk1.y, acc2g[ri][1]);
                        }
                    }
                }
            }
        }

        // ---- residual: h += z + b2f ----
        __syncthreads();
        if (!is_ffma) {
#pragma unroll
            for (int mt = 0; mt < 2; mt++)
#pragma unroll
                for (int j = 0; j < 4; j++) {
                    int col = wn * 32 + j * 8 + 2 * tg;
                    float bb0 = s_b2[col], bb1 = s_b2[col + 1];
                    int r = wm * 32 + mt * 16 + g;
                    float2 hv = *(float2*)&s_h[r * LDH + col];
                    hv.x += zacc[mt][j][0] + bb0;
                    hv.y += zacc[mt][j][1] + bb1;
                    *(float2*)&s_h[r * LDH + col] = hv;
                    float2 hw = *(float2*)&s_h[(r + 8) * LDH + col];
                    hw.x += zacc[mt][j][2] + bb0;
                    hw.y += zacc[mt][j][3] + bb1;
                    *(float2*)&s_h[(r + 8) * LDH + col] = hw;
                }
        } else {
#pragma unroll
            for (int ri = 0; ri < 8; ri++)
#pragma unroll
                for (int cp = 0; cp < 2; cp++) {
                    int col = 96 + ci0g + cp * 2;
                    float2 v = unpk(acc2g[ri][cp]);
                    float2 hv = *(float2*)&s_h[(r0 + ri) * LDH + col];
                    hv.x += v.x + s_b2[col];
                    hv.y += v.y + s_b2[col + 1];
                    *(float2*)&s_h[(r0 + ri) * LDH + col] = hv;
                }
        }
        __syncthreads();
    }

    // ============================ classifier + emit ============================
    {
        float2 cw[4];
#pragma unroll
        for (int ci = 0; ci < 4; ci++)
            cw[ci] = *(const float2*)(cls_w + (lane * 4 + ci) * 2);
        float cb0 = cls_b[0], cb1 = cls_b[1];
#pragma unroll
        for (int rr = 0; rr < 8; rr++) {
            int r = wid * 8 + rr;
            float4 v = *(const float4*)&s_h[r * LDH + lane * 4];
            float a0 = v.x * cw[0].x + v.y * cw[1].x + v.z * cw[2].x + v.w * cw[3].x;
            float a1 = v.x * cw[0].y + v.y * cw[1].y + v.z * cw[2].y + v.w * cw[3].y;
#pragma unroll
            for (int o = 16; o > 0; o >>= 1) {
                a0 += __shfl_xor_sync(0xffffffffu, a0, o);
                a1 += __shfl_xor_sync(0xffffffffu, a1, o);
            }
            if (lane == 0) {
                size_t row = row0 + r;
                out[row * 2]     = a0 + cb0;
                out[row * 2 + 1] = a1 + cb1;
            }
        }
        for (int i = tid; i < ROWS * 32; i += THREADS) {
            int r = i >> 5, c = (i & 31) * 4;
            *(float4*)&out[(size_t)B_TOTAL * 2 + (row0 + r) * DIM + c] =
                *(const float4*)&s_h[r * LDH + c];
        }
    }
}

// ---------------------------------------------------------------------------
extern "C" void kernel_launch(void* const* d_in, const int* in_sizes, int n_in,
                              void* d_out, int out_size) {
    const float* x      = (const float*)d_in[0];
    const float* proj_w = (const float*)d_in[1];
    const float* proj_b = (const float*)d_in[2];
    const float* pos    = (const float*)d_in[3];
    const float* sel_w  = (const float*)d_in[4];
    const float* sel_b  = (const float*)d_in[5];
    const float* ln_s   = (const float*)d_in[6];
    const float* ln_b   = (const float*)d_in[7];
    const float* w1     = (const float*)d_in[8];
    const float* b1     = (const float*)d_in[9];
    const float* w2     = (const float*)d_in[10];
    const float* b2     = (const float*)d_in[11];
    const float* gate   = (const float*)d_in[12];
    const float* cls_w  = (const float*)d_in[13];
    const float* cls_b  = (const float*)d_in[14];
    const float* tf     = (const float*)d_in[15];
    float* out = (float*)d_out;

    const int pilot_smem = 28832 * 4;   // 115328 B
    cudaFuncSetAttribute(pilot_kernel, cudaFuncAttributeMaxDynamicSharedMemorySize, pilot_smem);
    cudaFuncSetAttribute(fused_kernel, cudaFuncAttributeMaxDynamicSharedMemorySize, SMEM_TOT);

    pilot_kernel<<<1, 1024, pilot_smem>>>(x, proj_w, proj_b, pos, sel_w, sel_b, ln_s, ln_b,
                                          w1, b1, w2, b2, gate, tf);
    repack_kernel<<<40, 256>>>(w1, w2);
    fused_kernel<<<B_TOTAL / ROWS, THREADS, SMEM_TOT>>>(
        x, proj_w, proj_b, pos, b1, ln_s, ln_b, cls_w, cls_b, out);
}

// round 13
// speedup vs baseline: 1.2865x; 1.2865x over previous
#include <cuda_runtime.h>
#include <cuda_fp16.h>
#include <math.h>
#include <stdint.h>

#define B_TOTAL 131072
#define DIM     128
#define HID     256
#define NB      8
#define NL      4
#define KSEL    2
#define FIN     32
#define ROWS    128
#define LDH     132          // s_h float stride
#define TLW     68           // hn fp16 tile stride in 32-bit words (128 cols)
#define TLT     132          // t  fp16 tile stride in 32-bit words (256 cols)
#define THREADS 512

typedef unsigned long long u64;

__device__ int   g_sel[NL * KSEL];
__device__ float g_gfac[NL * KSEL][DIM];
__device__ float g_b2f[NL * KSEL][DIM];     // 0.5 * b2 * gfac
// fp16 tensor stream: 32 chunks x 24KB  [ks(8)][jp(6)][t(4)][nl(8)][k2(4)]
__device__ __align__(256) uint4 g_wpack[49152];
// fp32 FFMA stream: 8 slots x 16384 floats (G1 [k 128][ci 64] + G2 [k 256][ci 32])
__device__ __align__(256) float g_wf[131072];

__device__ __forceinline__ float sigm(float x) { return 1.0f / (1.0f + expf(-x)); }
__device__ __forceinline__ float gelu_exact(float x) {
    return 0.5f * x * (1.0f + erff(x * 0.70710678118654752440f));
}
__device__ __forceinline__ float gelu_fast(float x) {
    float u = fabsf(x) * 0.70710678118654752440f;
    float t = __fdividef(1.0f, fmaf(0.3275911f, u, 1.0f));
    float p = t * fmaf(t, fmaf(t, fmaf(t, fmaf(t, 1.061405429f, -1.453152027f),
                                       1.421413741f), -0.284496736f), 0.254829592f);
    float erfc_abs = p * __expf(-u * u);
    float er = copysignf(1.0f - erfc_abs, x);
    return 0.5f * x * (1.0f + er);
}
__device__ __forceinline__ uint32_t pkh2(float x, float y) {
    return (uint32_t)__half_as_ushort(__float2half_rn(x))
         | ((uint32_t)__half_as_ushort(__float2half_rn(y)) << 16);
}
__device__ __forceinline__ uint32_t pkf2(float lo, float hi) {
    uint32_t r;
    asm("cvt.rn.f16x2.f32 %0, %1, %2;" : "=r"(r) : "f"(hi), "f"(lo));
    return r;
}
__device__ __forceinline__ void cp16(uint32_t d, const void* s) {
    asm volatile("cp.async.cg.shared.global [%0], [%1], 16;" :: "r"(d), "l"(s));
}
__device__ __forceinline__ void mma_fp16(float c[4], uint32_t a0, uint32_t a1,
                                         uint32_t a2, uint32_t a3,
                                         uint32_t b0, uint32_t b1) {
    asm volatile("mma.sync.aligned.m16n8k16.row.col.f32.f16.f16.f32 "
        "{%0,%1,%2,%3},{%4,%5,%6,%7},{%8,%9},{%0,%1,%2,%3};"
        : "+f"(c[0]), "+f"(c[1]), "+f"(c[2]), "+f"(c[3])
        : "r"(a0), "r"(a1), "r"(a2), "r"(a3), "r"(b0), "r"(b1));
}
__device__ __forceinline__ void ldsm4(uint32_t r[4], uint32_t addr) {
    asm volatile("ldmatrix.sync.aligned.m8n8.x4.shared.b16 {%0,%1,%2,%3}, [%4];"
        : "=r"(r[0]), "=r"(r[1]), "=r"(r[2]), "=r"(r[3]) : "r"(addr));
}
__device__ __forceinline__ u64 ffma2v(u64 a, u64 b, u64 c) {
    u64 d; asm("fma.rn.f32x2 %0, %1, %2, %3;" : "=l"(d) : "l"(a), "l"(b), "l"(c)); return d;
}
__device__ __forceinline__ u64 pkaa(float a) {
    u64 r; asm("mov.b64 %0, {%1, %1};" : "=l"(r) : "f"(a)); return r;
}
__device__ __forceinline__ float2 unpk(u64 v) {
    float2 r; asm("mov.b64 {%0, %1}, %2;" : "=f"(r.x), "=f"(r.y) : "l"(v)); return r;
}
__device__ __forceinline__ void barcta() {
    asm volatile("bar.sync 0;" ::: "memory");
}

// ---------------------------------------------------------------------------
// Pilot (R11-proven)
// ---------------------------------------------------------------------------
__global__ void __launch_bounds__(1024, 1)
pilot_kernel(const float* __restrict__ x, const float* __restrict__ pw,
             const float* __restrict__ pb, const float* __restrict__ pos,
             const float* __restrict__ sel_w, const float* __restrict__ sel_b,
             const float* __restrict__ ln_s, const float* __restrict__ ln_b,
             const float* __restrict__ w1, const float* __restrict__ b1,
             const float* __restrict__ w2, const float* __restrict__ b2,
             const float* __restrict__ gate, const float* __restrict__ tf) {
    extern __shared__ float ps[];
    float* s_selw = ps;
    float* s_lns  = ps + 4096;
    float* s_lnb  = ps + 8192;
    float* s_b1a  = ps + 12288;
    float* s_b2a  = ps + 20480;
    float* s_gate = ps + 24576;
    float* s_tf   = ps + 28672;
    float* s_selb = ps + 28800;

    __shared__ float h0[DIM], hn[DIM], tbuf[HID], fbuf[DIM];
    __shared__ float part[8][256];
    __shared__ float redA[64], redB[64];
    __shared__ float sc[NB];
    __shared__ int   seli[KSEL];
    __shared__ float s_mu, s_rstd;
    int tid = threadIdx.x, lane = tid & 31, wid = tid >> 5;

    {
        ((float4*)s_selw)[tid & 1023] = ((const float4*)sel_w)[tid & 1023];
        ((float4*)s_lns)[tid & 1023]  = ((const float4*)ln_s)[tid & 1023];
        ((float4*)s_lnb)[tid & 1023]  = ((const float4*)ln_b)[tid & 1023];
        ((float4*)s_b1a)[tid]         = ((const float4*)b1)[tid];
        ((float4*)s_b1a)[tid + 1024]  = ((const float4*)b1)[tid + 1024];
        ((float4*)s_b2a)[tid & 1023]  = ((const float4*)b2)[tid & 1023];
        ((float4*)s_gate)[tid & 1023] = ((const float4*)gate)[tid & 1023];
        if (tid < 32) ((float4*)s_tf)[tid] = ((const float4*)tf)[tid];
        else if (tid < 40) ((float4*)s_selb)[tid - 32] = ((const float4*)sel_b)[tid - 32];
    }

    if (tid < DIM) {
        float acc = pb[tid] + pos[tid];
#pragma unroll
        for (int k = 0; k < FIN; k++) acc += x[k] * pw[k * DIM + tid];
        h0[tid] = acc;
    }
    __syncthreads();

    for (int l = 0; l < NL; l++) {
        {
            int b = tid >> 7, d = tid & 127;
            float pv = h0[d] * s_selw[(l * DIM + d) * NB + b];
#pragma unroll
            for (int o = 16; o > 0; o >>= 1) pv += __shfl_xor_sync(0xffffffffu, pv, o);
            if (lane == 0) part[0][wid] = pv;
        }
        __syncthreads();
        if (tid < NB) {
            float s = part[0][tid * 4] + part[0][tid * 4 + 1]
                    + part[0][tid * 4 + 2] + part[0][tid * 4 + 3];
            sc[tid] = sigm(s + s_selb[l * NB + tid]) * 0.6f + 0.2f;
        }
        __syncthreads();
        if (tid == 0) {
            int i0 = 0; float v0 = -1e30f;
            for (int j = 0; j < NB; j++) if (sc[j] > v0) { v0 = sc[j]; i0 = j; }
            int i1 = -1; float v1 = -1e30f;
            for (int j = 0; j < NB; j++) { if (j == i0) continue; if (sc[j] > v1) { v1 = sc[j]; i1 = j; } }
            seli[0] = i0; seli[1] = i1;
            g_sel[l * KSEL + 0] = i0; g_sel[l * KSEL + 1] = i1;
        }
        __syncthreads();

        for (int k = 0; k < KSEL; k++) {
            int i = seli[k];
            int bo = l * NB + i;
            if (tid < DIM) {
                float fv = 1.0f + sigm(s_gate[bo * DIM + tid]) * s_tf[tid];
                fbuf[tid] = fv;
                g_gfac[l * KSEL + k][tid] = fv;
                g_b2f[l * KSEL + k][tid] = 0.5f * s_b2a[bo * DIM + tid] * fv;
            }
            if (tid < 64) {
                float a = h0[tid], b = h0[tid + 64];
                redA[tid] = a + b; redB[tid] = a * a + b * b;
            }
            __syncthreads();
            if (tid == 0) {
                float s = 0.f, q = 0.f;
                for (int j = 0; j < 64; j++) { s += redA[j]; q += redB[j]; }
                float mu = s * (1.0f / DIM);
                s_mu = mu;
                s_rstd = rsqrtf(q * (1.0f / DIM) - mu * mu + 1e-5f);
            }
            __syncthreads();
            if (tid < DIM)
                hn[tid] = (h0[tid] - s_mu) * s_rstd * s_lns[bo * DIM + tid] + s_lnb[bo * DIM + tid];
            __syncthreads();
            {
                int col = tid & 255, seg = tid >> 8, k0 = seg * 32;
                const float* W1 = w1 + (size_t)bo * DIM * HID;
                float acc = 0.f;
#pragma unroll
                for (int kk = 0; kk < 32; kk++)
                    acc += hn[k0 + kk] * __ldg(&W1[(size_t)(k0 + kk) * HID + col]);
                part[seg][col] = acc;
            }
            __syncthreads();
            if (tid < HID)
                tbuf[tid] = gelu_exact(part[0][tid] + part[1][tid] + part[2][tid] + part[3][tid]
                                       + s_b1a[bo * HID + tid]);
            __syncthreads();
            {
                int col = tid & 127, seg = tid >> 7, k0 = seg * 32;
                const float* W2 = w2 + (size_t)bo * HID * DIM;
                float acc = 0.f;
#pragma unroll
                for (int kk = 0; kk < 32; kk++)
                    acc += tbuf[k0 + kk] * __ldg(&W2[(size_t)(k0 + kk) * DIM + col]);
                part[seg][col] = acc;
            }
            __syncthreads();
            if (tid < DIM) {
                float z = part[0][tid] + part[1][tid] + part[2][tid] + part[3][tid]
                        + part[4][tid] + part[5][tid] + part[6][tid] + part[7][tid]
                        + s_b2a[bo * DIM + tid];
                h0[tid] += 0.5f * z * fbuf[tid];
            }
            __syncthreads();
        }
    }
}

// ---------------------------------------------------------------------------
// Repack (R12-validated layouts)
// ---------------------------------------------------------------------------
__global__ void repack_kernel(const float* __restrict__ w1g, const float* __restrict__ w2g) {
    int blkid = blockIdx.x;
    if (blkid < 32) {
        int q = blkid;
        int slot = q >> 2, ph = q & 3;
        int blk = g_sel[slot];
        size_t bo = (size_t)((slot >> 1) * NB + blk);
        bool isG2 = (ph >= 2);
        const float* W = isG2 ? (w2g + bo * HID * DIM) : (w1g + bo * DIM * HID);
        int ld = isG2 ? DIM : HID;
        uint32_t* dst = (uint32_t*)g_wpack + (size_t)q * 6144;
        for (int e2 = threadIdx.x; e2 < 6144; e2 += 256) {
            int k2 = e2 & 3, nl = (e2 >> 2) & 7, t = (e2 >> 5) & 3;
            int gidx = e2 >> 7;
            int jp = gidx % 6, ks = gidx / 6;
            int j = jp * 2 + (t >> 1), kh = t & 1;
            int kl = ks * 16 + kh * 8 + k2 * 2;
            int k, n; float scl = 1.0f;
            if (!isG2) { k = kl; n = ph * 96 + j * 8 + nl; }
            else       { k = (ph - 2) * 128 + kl; n = j * 8 + nl;
                         scl = 0.5f * g_gfac[slot][n]; }
            dst[e2] = pkh2(W[(size_t)k * ld + n] * scl, W[(size_t)(k + 1) * ld + n] * scl);
        }
    } else {
        int slot = blkid - 32;
        int blk = g_sel[slot];
        size_t bo = (size_t)((slot >> 1) * NB + blk);
        const float* W1 = w1g + bo * DIM * HID;
        const float* W2 = w2g + bo * HID * DIM;
        float* dst = g_wf + (size_t)slot * 16384;
        for (int f = threadIdx.x; f < 16384; f += 256) {
            float v;
            if (f < 8192) {
                int k = f >> 6, ci = f & 63;
                v = W1[(size_t)k * HID + 192 + ci];
            } else {
                int f2 = f - 8192;
                int k = f2 >> 5, ci = f2 & 31;
                v = W2[(size_t)k * DIM + 96 + ci] * 0.5f * g_gfac[slot][96 + ci];
            }
            dst[f] = v;
        }
    }
}

// ---------------------------------------------------------------------------
#define OFF_H    0
#define OFF_HN   67584
#define OFF_T    102400
#define OFF_WB   169984
#define OFF_B1   219136
#define OFF_B2   220160
#define SMEM_TOT 220672

// ---------------------------------------------------------------------------
// Fused: 12 tensor warps + 4 FFMA warps, disjoint role branches (no spills)
// ---------------------------------------------------------------------------
__global__ void __launch_bounds__(THREADS, 1)
fused_kernel(const float* __restrict__ xg, const float* __restrict__ pw,
             const float* __restrict__ pb, const float* __restrict__ pos,
             const float* __restrict__ b1g,
             const float* __restrict__ ln_s, const float* __restrict__ ln_b,
             const float* __restrict__ cls_w, const float* __restrict__ cls_b,
             float* __restrict__ out) {
    extern __shared__ char smem[];
    float*    s_h  = (float*)(smem + OFF_H);
    uint32_t* hn32 = (uint32_t*)(smem + OFF_HN);
    uint32_t* t32  = (uint32_t*)(smem + OFF_T);
    float*    s_b1 = (float*)(smem + OFF_B1);
    float*    s_b2 = (float*)(smem + OFF_B2);

    int tid = threadIdx.x, lane = tid & 31, wid = tid >> 5;
    int wm = wid & 3, wn = wid >> 2;          // wn 0..2 tensor, wn==3 FFMA
    bool is_ffma = (wn == 3);
    int g = lane >> 2, tg = lane & 3;
    size_t row0 = (size_t)blockIdx.x * ROWS;

    uint32_t base = (uint32_t)__cvta_generic_to_shared(smem);
    uint32_t hnb = base + OFF_HN;
    uint32_t tb  = base + OFF_T;
    uint32_t wb  = base + OFF_WB;

    uint32_t aoffH = (uint32_t)(((wm * 32 + (lane & 15)) * TLW + (lane >> 4) * 4) * 4);
    uint32_t aoffT = (uint32_t)(((wm * 32 + (lane & 15)) * TLT + (lane >> 4) * 4) * 4);
    uint32_t boff  = (uint32_t)(wn * 1024 + lane * 16);
    int r0  = wm * 32 + (lane >> 3) * 8;
    int ci0 = (lane & 7) * 8;
    int ci0g = (lane & 7) * 4;

    // prefetch chunk 0
    {
        uint32_t d = wb + tid * 16;
        const char* s = (const char*)g_wpack + tid * 16;
        cp16(d, s); cp16(d + 8192, s + 8192); cp16(d + 16384, s + 16384);
        asm volatile("cp.async.commit_group;");
    }

    // ================= input projection =================
    {
        float* s_x  = (float*)(smem + OFF_HN);
        float* s_pw = (float*)(smem + OFF_T);
        for (int i = tid; i < 1024; i += THREADS) {
            int r = i >> 5, c4 = i & 31;
            *(float4*)&s_pw[r * LDH + c4 * 4] = *(const float4*)(pw + r * DIM + c4 * 4);
        }
        for (int i = tid; i < 1024; i += THREADS) {
            int r = i >> 3, c4 = i & 7;
            *(float4*)&s_x[r * 36 + c4 * 4] = *(const float4*)(xg + (row0 + r) * FIN + c4 * 4);
        }
        __syncthreads();
        int pr = tid >> 2, qt = tid & 3;
        int colb = qt * 32;
        float4 acc[8];
#pragma unroll
        for (int c4 = 0; c4 < 8; c4++) {
            int col = colb + c4 * 4;
            float4 a = *(const float4*)(pb + col);
            float4 po = *(const float4*)(pos + col);
            acc[c4].x = a.x + po.x; acc[c4].y = a.y + po.y;
            acc[c4].z = a.z + po.z; acc[c4].w = a.w + po.w;
        }
#pragma unroll 8
        for (int k = 0; k < FIN; k++) {
            float a = s_x[pr * 36 + k];
#pragma unroll
            for (int c4 = 0; c4 < 8; c4++) {
                float4 w = *(const float4*)&s_pw[k * LDH + colb + c4 * 4];
                acc[c4].x += a * w.x; acc[c4].y += a * w.y;
                acc[c4].z += a * w.z; acc[c4].w += a * w.w;
            }
        }
        __syncthreads();
#pragma unroll
        for (int c4 = 0; c4 < 8; c4++)
            *(float4*)&s_h[pr * LDH + colb + c4 * 4] = acc[c4];
        __syncthreads();
    }

    // ============================ 8 expert slots ============================
    for (int slot = 0; slot < NL * KSEL; slot++) {
        int blk = g_sel[slot];
        size_t bo = (size_t)((slot >> 1) * NB + blk);
        const float* LS = ln_s + bo * DIM;
        const float* LB = ln_b + bo * DIM;
        if (tid < HID) s_b1[tid] = __ldg(b1g + bo * HID + tid);
        else if (tid < HID + DIM) s_b2[tid - HID] = g_b2f[slot][tid - HID];

        // ---- LayerNorm -> hn32 (all warps) ----
        {
            float4 ls4 = *(const float4*)(LS + lane * 4);
            float4 lb4 = *(const float4*)(LB + lane * 4);
#pragma unroll
            for (int rr = 0; rr < 8; rr++) {
                int r = wid * 8 + rr;
                float4 v = *(const float4*)&s_h[r * LDH + lane * 4];
                float s = v.x + v.y + v.z + v.w;
                float q = v.x * v.x + v.y * v.y + v.z * v.z + v.w * v.w;
#pragma unroll
                for (int o = 16; o > 0; o >>= 1) {
                    s += __shfl_xor_sync(0xffffffffu, s, o);
                    q += __shfl_xor_sync(0xffffffffu, q, o);
                }
                float mu = s * (1.0f / DIM);
                float rstd = rsqrtf(q * (1.0f / DIM) - mu * mu + 1e-5f);
                uint2 pk;
                pk.x = pkf2((v.x - mu) * rstd * ls4.x + lb4.x,
                            (v.y - mu) * rstd * ls4.y + lb4.y);
                pk.y = pkf2((v.z - mu) * rstd * ls4.z + lb4.z,
                            (v.w - mu) * rstd * ls4.w + lb4.w);
                *(uint2*)&hn32[r * TLW + lane * 2] = pk;
            }
        }

        if (!is_ffma) {
            // ================= TENSOR role: full phase loop =================
            float zacc[2][4][4];
#pragma unroll
            for (int mt = 0; mt < 2; mt++)
#pragma unroll
                for (int j = 0; j < 4; j++)
#pragma unroll
                    for (int e = 0; e < 4; e++) zacc[mt][j][e] = 0.0f;

            for (int ph = 0; ph < 4; ph++) {
                int q = slot * 4 + ph;
                asm volatile("cp.async.wait_group 0;" ::: "memory");
                barcta();
                {
                    int nq = q + 1;
                    if (nq < 32) {
                        uint32_t d = wb + (nq & 1) * 24576 + tid * 16;
                        const char* s = (const char*)g_wpack + (size_t)nq * 24576 + tid * 16;
                        cp16(d, s); cp16(d + 8192, s + 8192); cp16(d + 16384, s + 16384);
                    }
                    asm volatile("cp.async.commit_group;");
                }
                uint32_t wbc = wb + (q & 1) * 24576;
                bool isG1 = (ph < 2);
                uint32_t Ab = isG1 ? (hnb + aoffH)
                                   : (tb + aoffT + (ph == 3 ? 256u : 0u));
                uint32_t astr = isG1 ? (16 * TLW * 4) : (16 * TLT * 4);

                float c1[2][4][4];
                if (isG1) {
#pragma unroll
                    for (int mt = 0; mt < 2; mt++)
#pragma unroll
                        for (int j = 0; j < 4; j++)
#pragma unroll
                            for (int e = 0; e < 4; e++) c1[mt][j][e] = 0.0f;
                }
                float (*acc)[4][4] = isG1 ? c1 : zacc;

#pragma unroll
                for (int ks = 0; ks < 8; ks++) {
                    uint32_t b0[4], b1f[4];
                    ldsm4(b0,  wbc + boff + ks * 3072);
                    ldsm4(b1f, wbc + boff + ks * 3072 + 512);
                    uint32_t a0[4], a1[4];
                    ldsm4(a0, Ab + ks * 32);
                    ldsm4(a1, Ab + ks * 32 + astr);
#pragma unroll
                    for (int j = 0; j < 4; j++) {
                        uint32_t fb0 = (j < 2) ? b0[(j & 1) * 2]     : b1f[(j & 1) * 2];
                        uint32_t fb1 = (j < 2) ? b0[(j & 1) * 2 + 1] : b1f[(j & 1) * 2 + 1];
                        mma_fp16(acc[0][j], a0[0], a0[1], a0[2], a0[3], fb0, fb1);
                        mma_fp16(acc[1][j], a1[0], a1[1], a1[2], a1[3], fb0, fb1);
                    }
                }

                if (isG1) {
#pragma unroll
                    for (int mt = 0; mt < 2; mt++)
#pragma unroll
                        for (int j = 0; j < 4; j++) {
                            int colp = ph * 96 + wn * 32 + j * 8 + 2 * tg;
                            float bb0 = s_b1[colp];
                            float bb1 = s_b1[colp + 1];
                            int r = wm * 32 + mt * 16 + g;
                            int cw = ph * 48 + wn * 16 + j * 4 + tg;
                            t32[r * TLT + cw] =
                                pkf2(gelu_fast(c1[mt][j][0] + bb0), gelu_fast(c1[mt][j][1] + bb1));
                            t32[(r + 8) * TLT + cw] =
                                pkf2(gelu_fast(c1[mt][j][2] + bb0), gelu_fast(c1[mt][j][3] + bb1));
                        }
                }
            }

            barcta();
            // residual (tensor cols 0..95)
#pragma unroll
            for (int mt = 0; mt < 2; mt++)
#pragma unroll
                for (int j = 0; j < 4; j++) {
                    int col = wn * 32 + j * 8 + 2 * tg;
                    float bb0 = s_b2[col], bb1 = s_b2[col + 1];
                    int r = wm * 32 + mt * 16 + g;
                    float2 hv = *(float2*)&s_h[r * LDH + col];
                    hv.x += zacc[mt][j][0] + bb0;
                    hv.y += zacc[mt][j][1] + bb1;
                    *(float2*)&s_h[r * LDH + col] = hv;
                    float2 hw = *(float2*)&s_h[(r + 8) * LDH + col];
                    hw.x += zacc[mt][j][2] + bb0;
                    hw.y += zacc[mt][j][3] + bb1;
                    *(float2*)&s_h[(r + 8) * LDH + col] = hw;
                }
            barcta();
        } else {
            // ================= FFMA role: two scoped sub-loops =================
            {   // --- G1 slice (cols 192..255), phases 0..1 ---
                u64 acc1[8][4];
#pragma unroll
                for (int ri = 0; ri < 8; ri++)
#pragma unroll
                    for (int c = 0; c < 4; c++) acc1[ri][c] = 0ULL;

                for (int ph = 0; ph < 2; ph++) {
                    int q = slot * 4 + ph;
                    asm volatile("cp.async.wait_group 0;" ::: "memory");
                    barcta();
                    {
                        int nq = q + 1;
                        if (nq < 32) {
                            uint32_t d = wb + (nq & 1) * 24576 + tid * 16;
                            const char* s = (const char*)g_wpack + (size_t)nq * 24576 + tid * 16;
                            cp16(d, s); cp16(d + 8192, s + 8192); cp16(d + 16384, s + 16384);
                        }
                        asm volatile("cp.async.commit_group;");
                    }
                    const float* WB1 = g_wf + (size_t)slot * 16384;
                    int kp0 = ph * 32, kp1 = kp0 + 32;
                    for (int kp = kp0; kp < kp1; kp++) {
                        const float* bp = WB1 + (2 * kp) * 64 + ci0;
                        ulonglong2 b00 = *(const ulonglong2*)(bp);
                        ulonglong2 b01 = *(const ulonglong2*)(bp + 4);
                        ulonglong2 b10 = *(const ulonglong2*)(bp + 64);
                        ulonglong2 b11 = *(const ulonglong2*)(bp + 68);
#pragma unroll
                        for (int ri = 0; ri < 8; ri++) {
                            uint32_t w = hn32[(r0 + ri) * TLW + kp];
                            float2 af = __half22float2(*(__half2*)&w);
                            u64 a = pkaa(af.x);
                            acc1[ri][0] = ffma2v(a, b00.x, acc1[ri][0]);
                            acc1[ri][1] = ffma2v(a, b00.y, acc1[ri][1]);
                            acc1[ri][2] = ffma2v(a, b01.x, acc1[ri][2]);
                            acc1[ri][3] = ffma2v(a, b01.y, acc1[ri][3]);
                            u64 ah = pkaa(af.y);
                            acc1[ri][0] = ffma2v(ah, b10.x, acc1[ri][0]);
                            acc1[ri][1] = ffma2v(ah, b10.y, acc1[ri][1]);
                            acc1[ri][2] = ffma2v(ah, b11.x, acc1[ri][2]);
                            acc1[ri][3] = ffma2v(ah, b11.y, acc1[ri][3]);
                        }
                    }
                }
                // GELU + store t cols 192..255
#pragma unroll
                for (int ri = 0; ri < 8; ri++) {
                    uint32_t w[4];
#pragma unroll
                    for (int cp = 0; cp < 4; cp++) {
                        float2 v = unpk(acc1[ri][cp]);
                        int col = 192 + ci0 + cp * 2;
                        w[cp] = pkf2(gelu_fast(v.x + s_b1[col]),
                                     gelu_fast(v.y + s_b1[col + 1]));
                    }
                    *(uint4*)&t32[(r0 + ri) * TLT + 96 + (ci0 >> 1)] =
                        make_uint4(w[0], w[1], w[2], w[3]);
                }
            }
            {   // --- G2 slice (cols 96..127), phases 2..3 ---
                u64 acc2g[8][2];
#pragma unroll
                for (int ri = 0; ri < 8; ri++) { acc2g[ri][0] = 0ULL; acc2g[ri][1] = 0ULL; }

                for (int ph = 2; ph < 4; ph++) {
                    int q = slot * 4 + ph;
                    asm volatile("cp.async.wait_group 0;" ::: "memory");
                    barcta();
                    {
                        int nq = q + 1;
                        if (nq < 32) {
                            uint32_t d = wb + (nq & 1) * 24576 + tid * 16;
                            const char* s = (const char*)g_wpack + (size_t)nq * 24576 + tid * 16;
                            cp16(d, s); cp16(d + 8192, s + 8192); cp16(d + 16384, s + 16384);
                        }
                        asm volatile("cp.async.commit_group;");
                    }
                    const float* WB2 = g_wf + (size_t)slot * 16384 + 8192;
                    int kp0 = (ph - 2) * 64, kp1 = kp0 + 64;
                    for (int kp = kp0; kp < kp1; kp++) {
                        const float* bp = WB2 + (2 * kp) * 32 + ci0g;
                        ulonglong2 bk0 = *(const ulonglong2*)(bp);
                        ulonglong2 bk1 = *(const ulonglong2*)(bp + 32);
#pragma unroll
                        for (int ri = 0; ri < 8; ri++) {
                            uint32_t w = t32[(r0 + ri) * TLT + kp];
                            float2 af = __half22float2(*(__half2*)&w);
                            u64 a = pkaa(af.x);
                            acc2g[ri][0] = ffma2v(a, bk0.x, acc2g[ri][0]);
                            acc2g[ri][1] = ffma2v(a, bk0.y, acc2g[ri][1]);
                            u64 ah = pkaa(af.y);
                            acc2g[ri][0] = ffma2v(ah, bk1.x, acc2g[ri][0]);
                            acc2g[ri][1] = ffma2v(ah, bk1.y, acc2g[ri][1]);
                        }
                    }
                }

                barcta();
                // residual (FFMA cols 96..127)
#pragma unroll
                for (int ri = 0; ri < 8; ri++)
#pragma unroll
                    for (int cp = 0; cp < 2; cp++) {
                        int col = 96 + ci0g + cp * 2;
                        float2 v = unpk(acc2g[ri][cp]);
                        float2 hv = *(float2*)&s_h[(r0 + ri) * LDH + col];
                        hv.x += v.x + s_b2[col];
                        hv.y += v.y + s_b2[col + 1];
                        *(float2*)&s_h[(r0 + ri) * LDH + col] = hv;
                    }
                barcta();
            }
        }
    }

    // ============================ classifier + emit ============================
    {
        float2 cw[4];
#pragma unroll
        for (int ci = 0; ci < 4; ci++)
            cw[ci] = *(const float2*)(cls_w + (lane * 4 + ci) * 2);
        float cb0 = cls_b[0], cb1 = cls_b[1];
#pragma unroll
        for (int rr = 0; rr < 8; rr++) {
            int r = wid * 8 + rr;
            float4 v = *(const float4*)&s_h[r * LDH + lane * 4];
            float a0 = v.x * cw[0].x + v.y * cw[1].x + v.z * cw[2].x + v.w * cw[3].x;
            float a1 = v.x * cw[0].y + v.y * cw[1].y + v.z * cw[2].y + v.w * cw[3].y;
#pragma unroll
            for (int o = 16; o > 0; o >>= 1) {
                a0 += __shfl_xor_sync(0xffffffffu, a0, o);
                a1 += __shfl_xor_sync(0xffffffffu, a1, o);
            }
            if (lane == 0) {
                size_t row = row0 + r;
                out[row * 2]     = a0 + cb0;
                out[row * 2 + 1] = a1 + cb1;
            }
        }
        for (int i = tid; i < ROWS * 32; i += THREADS) {
            int r = i >> 5, c = (i & 31) * 4;
            *(float4*)&out[(size_t)B_TOTAL * 2 + (row0 + r) * DIM + c] =
                *(const float4*)&s_h[r * LDH + c];
        }
    }
}

// ---------------------------------------------------------------------------
extern "C" void kernel_launch(void* const* d_in, const int* in_sizes, int n_in,
                              void* d_out, int out_size) {
    const float* x      = (const float*)d_in[0];
    const float* proj_w = (const float*)d_in[1];
    const float* proj_b = (const float*)d_in[2];
    const float* pos    = (const float*)d_in[3];
    const float* sel_w  = (const float*)d_in[4];
    const float* sel_b  = (const float*)d_in[5];
    const float* ln_s   = (const float*)d_in[6];
    const float* ln_b   = (const float*)d_in[7];
    const float* w1     = (const float*)d_in[8];
    const float* b1     = (const float*)d_in[9];
    const float* w2     = (const float*)d_in[10];
    const float* b2     = (const float*)d_in[11];
    const float* gate   = (const float*)d_in[12];
    const float* cls_w  = (const float*)d_in[13];
    const float* cls_b  = (const float*)d_in[14];
    const float* tf     = (const float*)d_in[15];
    float* out = (float*)d_out;

    const int pilot_smem = 28832 * 4;
    cudaFuncSetAttribute(pilot_kernel, cudaFuncAttributeMaxDynamicSharedMemorySize, pilot_smem);
    cudaFuncSetAttribute(fused_kernel, cudaFuncAttributeMaxDynamicSharedMemorySize, SMEM_TOT);

    pilot_kernel<<<1, 1024, pilot_smem>>>(x, proj_w, proj_b, pos, sel_w, sel_b, ln_s, ln_b,
                                          w1, b1, w2, b2, gate, tf);
    repack_kernel<<<40, 256>>>(w1, w2);
    fused_kernel<<<B_TOTAL / ROWS, THREADS, SMEM_TOT>>>(
        x, proj_w, proj_b, pos, b1, ln_s, ln_b, cls_w, cls_b, out);
}

// round 14
// speedup vs baseline: 5.4136x; 4.2080x over previous
#include <cuda_runtime.h>
#include <cuda_fp16.h>
#include <math.h>
#include <stdint.h>

#define B_TOTAL 131072
#define DIM     128
#define HID     256
#define NB      8
#define NL      4
#define KSEL    2
#define FIN     32
#define ROWS    64           // rows per CTA tile (2 CTA/SM)
#define LDH     132          // s_h float stride
#define TLW     68           // fp16 tile stride in 32-bit words
#define THREADS 256

typedef unsigned long long u64;

__device__ int   g_sel[NL * KSEL];
__device__ float g_gfac[NL * KSEL][DIM];
__device__ float g_b2f[NL * KSEL][DIM];     // 0.5 * b2 * gfac
// 32 chunks x 32KB: [ks(8)][jp(8)][tile4][8n][8k] fp16 tiles (R8/R11 layout)
__device__ __align__(256) uint4 g_wpack[65536];

__device__ __forceinline__ float sigm(float x) { return 1.0f / (1.0f + expf(-x)); }
__device__ __forceinline__ float gelu_exact(float x) {
    return 0.5f * x * (1.0f + erff(x * 0.70710678118654752440f));
}
__device__ __forceinline__ float gelu_fast(float x) {
    float u = fabsf(x) * 0.70710678118654752440f;
    float t = __fdividef(1.0f, fmaf(0.3275911f, u, 1.0f));
    float p = t * fmaf(t, fmaf(t, fmaf(t, fmaf(t, 1.061405429f, -1.453152027f),
                                       1.421413741f), -0.284496736f), 0.254829592f);
    float erfc_abs = p * __expf(-u * u);
    float er = copysignf(1.0f - erfc_abs, x);
    return 0.5f * x * (1.0f + er);
}
__device__ __forceinline__ uint32_t pkh2(float x, float y) {
    return (uint32_t)__half_as_ushort(__float2half_rn(x))
         | ((uint32_t)__half_as_ushort(__float2half_rn(y)) << 16);
}
__device__ __forceinline__ uint32_t pkf2(float lo, float hi) {
    uint32_t r;
    asm("cvt.rn.f16x2.f32 %0, %1, %2;" : "=r"(r) : "f"(hi), "f"(lo));
    return r;
}
__device__ __forceinline__ void cp16(uint32_t d, const void* s) {
    asm volatile("cp.async.cg.shared.global [%0], [%1], 16;" :: "r"(d), "l"(s));
}
__device__ __forceinline__ void mma_fp16(float c[4], uint32_t a0, uint32_t a1,
                                         uint32_t a2, uint32_t a3,
                                         uint32_t b0, uint32_t b1) {
    asm volatile("mma.sync.aligned.m16n8k16.row.col.f32.f16.f16.f32 "
        "{%0,%1,%2,%3},{%4,%5,%6,%7},{%8,%9},{%0,%1,%2,%3};"
        : "+f"(c[0]), "+f"(c[1]), "+f"(c[2]), "+f"(c[3])
        : "r"(a0), "r"(a1), "r"(a2), "r"(a3), "r"(b0), "r"(b1));
}
__device__ __forceinline__ void ldsm4(uint32_t r[4], uint32_t addr) {
    asm volatile("ldmatrix.sync.aligned.m8n8.x4.shared.b16 {%0,%1,%2,%3}, [%4];"
        : "=r"(r[0]), "=r"(r[1]), "=r"(r[2]), "=r"(r[3]) : "r"(addr));
}

// ---------------------------------------------------------------------------
// Pilot (R11-proven, byte-identical)
// ---------------------------------------------------------------------------
__global__ void __launch_bounds__(1024, 1)
pilot_kernel(const float* __restrict__ x, const float* __restrict__ pw,
             const float* __restrict__ pb, const float* __restrict__ pos,
             const float* __restrict__ sel_w, const float* __restrict__ sel_b,
             const float* __restrict__ ln_s, const float* __restrict__ ln_b,
             const float* __restrict__ w1, const float* __restrict__ b1,
             const float* __restrict__ w2, const float* __restrict__ b2,
             const float* __restrict__ gate, const float* __restrict__ tf) {
    extern __shared__ float ps[];
    float* s_selw = ps;
    float* s_lns  = ps + 4096;
    float* s_lnb  = ps + 8192;
    float* s_b1a  = ps + 12288;
    float* s_b2a  = ps + 20480;
    float* s_gate = ps + 24576;
    float* s_tf   = ps + 28672;
    float* s_selb = ps + 28800;

    __shared__ float h0[DIM], hn[DIM], tbuf[HID], fbuf[DIM];
    __shared__ float part[8][256];
    __shared__ float redA[64], redB[64];
    __shared__ float sc[NB];
    __shared__ int   seli[KSEL];
    __shared__ float s_mu, s_rstd;
    int tid = threadIdx.x, lane = tid & 31, wid = tid >> 5;

    {
        ((float4*)s_selw)[tid & 1023] = ((const float4*)sel_w)[tid & 1023];
        ((float4*)s_lns)[tid & 1023]  = ((const float4*)ln_s)[tid & 1023];
        ((float4*)s_lnb)[tid & 1023]  = ((const float4*)ln_b)[tid & 1023];
        ((float4*)s_b1a)[tid]         = ((const float4*)b1)[tid];
        ((float4*)s_b1a)[tid + 1024]  = ((const float4*)b1)[tid + 1024];
        ((float4*)s_b2a)[tid & 1023]  = ((const float4*)b2)[tid & 1023];
        ((float4*)s_gate)[tid & 1023] = ((const float4*)gate)[tid & 1023];
        if (tid < 32) ((float4*)s_tf)[tid] = ((const float4*)tf)[tid];
        else if (tid < 40) ((float4*)s_selb)[tid - 32] = ((const float4*)sel_b)[tid - 32];
    }

    if (tid < DIM) {
        float acc = pb[tid] + pos[tid];
#pragma unroll
        for (int k = 0; k < FIN; k++) acc += x[k] * pw[k * DIM + tid];
        h0[tid] = acc;
    }
    __syncthreads();

    for (int l = 0; l < NL; l++) {
        {
            int b = tid >> 7, d = tid & 127;
            float pv = h0[d] * s_selw[(l * DIM + d) * NB + b];
#pragma unroll
            for (int o = 16; o > 0; o >>= 1) pv += __shfl_xor_sync(0xffffffffu, pv, o);
            if (lane == 0) part[0][wid] = pv;
        }
        __syncthreads();
        if (tid < NB) {
            float s = part[0][tid * 4] + part[0][tid * 4 + 1]
                    + part[0][tid * 4 + 2] + part[0][tid * 4 + 3];
            sc[tid] = sigm(s + s_selb[l * NB + tid]) * 0.6f + 0.2f;
        }
        __syncthreads();
        if (tid == 0) {
            int i0 = 0; float v0 = -1e30f;
            for (int j = 0; j < NB; j++) if (sc[j] > v0) { v0 = sc[j]; i0 = j; }
            int i1 = -1; float v1 = -1e30f;
            for (int j = 0; j < NB; j++) { if (j == i0) continue; if (sc[j] > v1) { v1 = sc[j]; i1 = j; } }
            seli[0] = i0; seli[1] = i1;
            g_sel[l * KSEL + 0] = i0; g_sel[l * KSEL + 1] = i1;
        }
        __syncthreads();

        for (int k = 0; k < KSEL; k++) {
            int i = seli[k];
            int bo = l * NB + i;
            if (tid < DIM) {
                float fv = 1.0f + sigm(s_gate[bo * DIM + tid]) * s_tf[tid];
                fbuf[tid] = fv;
                g_gfac[l * KSEL + k][tid] = fv;
                g_b2f[l * KSEL + k][tid] = 0.5f * s_b2a[bo * DIM + tid] * fv;
            }
            if (tid < 64) {
                float a = h0[tid], b = h0[tid + 64];
                redA[tid] = a + b; redB[tid] = a * a + b * b;
            }
            __syncthreads();
            if (tid == 0) {
                float s = 0.f, q = 0.f;
                for (int j = 0; j < 64; j++) { s += redA[j]; q += redB[j]; }
                float mu = s * (1.0f / DIM);
                s_mu = mu;
                s_rstd = rsqrtf(q * (1.0f / DIM) - mu * mu + 1e-5f);
            }
            __syncthreads();
            if (tid < DIM)
                hn[tid] = (h0[tid] - s_mu) * s_rstd * s_lns[bo * DIM + tid] + s_lnb[bo * DIM + tid];
            __syncthreads();
            {
                int col = tid & 255, seg = tid >> 8, k0 = seg * 32;
                const float* W1 = w1 + (size_t)bo * DIM * HID;
                float acc = 0.f;
#pragma unroll
                for (int kk = 0; kk < 32; kk++)
                    acc += hn[k0 + kk] * __ldg(&W1[(size_t)(k0 + kk) * HID + col]);
                part[seg][col] = acc;
            }
            __syncthreads();
            if (tid < HID)
                tbuf[tid] = gelu_exact(part[0][tid] + part[1][tid] + part[2][tid] + part[3][tid]
                                       + s_b1a[bo * HID + tid]);
            __syncthreads();
            {
                int col = tid & 127, seg = tid >> 7, k0 = seg * 32;
                const float* W2 = w2 + (size_t)bo * HID * DIM;
                float acc = 0.f;
#pragma unroll
                for (int kk = 0; kk < 32; kk++)
                    acc += tbuf[k0 + kk] * __ldg(&W2[(size_t)(k0 + kk) * DIM + col]);
                part[seg][col] = acc;
            }
            __syncthreads();
            if (tid < DIM) {
                float z = part[0][tid] + part[1][tid] + part[2][tid] + part[3][tid]
                        + part[4][tid] + part[5][tid] + part[6][tid] + part[7][tid]
                        + s_b2a[bo * DIM + tid];
                h0[tid] += 0.5f * z * fbuf[tid];
            }
            __syncthreads();
        }
    }
}

// ---------------------------------------------------------------------------
// Repack (R11-proven): W1/W2 -> ldmatrix tile stream, W2 folded with 0.5*gfac
// chunk q = slot*4 + phase; phase = half*2 + g2
// ---------------------------------------------------------------------------
__global__ void repack_kernel(const float* __restrict__ w1g, const float* __restrict__ w2g) {
    int q = blockIdx.x;                 // 0..31
    int slot = q >> 2, phase = q & 3;
    int half = phase >> 1;
    bool isG2 = phase & 1;
    int blk = g_sel[slot];
    size_t bo = (size_t)((slot >> 1) * NB + blk);
    const float* W = isG2 ? (w2g + bo * HID * DIM) : (w1g + bo * DIM * HID);
    int ld = isG2 ? DIM : HID;
    uint32_t* dst = (uint32_t*)g_wpack + (size_t)q * 8192;
    for (int e2 = threadIdx.x; e2 < 8192; e2 += 256) {
        int k2 = e2 & 3, nl = (e2 >> 2) & 7, t = (e2 >> 5) & 3;
        int jp = (e2 >> 7) & 7, ks = e2 >> 10;
        int j = jp * 2 + (t >> 1), kh = t & 1, kl = k2 * 2;
        int k, n;
        float scl = 1.0f;
        if (!isG2) { k = ks * 16 + kh * 8 + kl; n = half * 128 + j * 8 + nl; }
        else       { k = half * 128 + ks * 16 + kh * 8 + kl; n = j * 8 + nl;
                     scl = 0.5f * g_gfac[slot][n]; }
        dst[e2] = pkh2(W[(size_t)k * ld + n] * scl, W[(size_t)(k + 1) * ld + n] * scl);
    }
}

// ---------------------------------------------------------------------------
// SMEM byte offsets (64-row tile; total 100.5 KB -> 2 CTA/SM)
// ---------------------------------------------------------------------------
#define OFF_H    0                    // 64*132*4 = 33792
#define OFF_HN   33792                // 64*68*4  = 17408
#define OFF_T    51200                // 64*68*4  = 17408
#define OFF_WB   68608                // 2 x 16384 = 32768
#define OFF_B1   101376               // 1024
#define OFF_B2   102400               // 512
#define SMEM_TOT 102912

// ---------------------------------------------------------------------------
// Fused: 64-row tiles, 8 warps (4m x 2n), 2 CTA/SM, 16KB weight sub-chunks
// ---------------------------------------------------------------------------
__global__ void __launch_bounds__(THREADS, 2)
fused_kernel(const float* __restrict__ xg, const float* __restrict__ pw,
             const float* __restrict__ pb, const float* __restrict__ pos,
             const float* __restrict__ b1g,
             const float* __restrict__ ln_s, const float* __restrict__ ln_b,
             const float* __restrict__ cls_w, const float* __restrict__ cls_b,
             float* __restrict__ out) {
    extern __shared__ char smem[];
    float*    s_h  = (float*)(smem + OFF_H);
    uint32_t* hn32 = (uint32_t*)(smem + OFF_HN);
    uint32_t* t32  = (uint32_t*)(smem + OFF_T);
    float*    s_b1 = (float*)(smem + OFF_B1);
    float*    s_b2 = (float*)(smem + OFF_B2);

    int tid = threadIdx.x, lane = tid & 31, wid = tid >> 5;
    int wm = wid & 3, wn = wid >> 2;          // 4 m-warps x 2 n-warps
    int g = lane >> 2, tg = lane & 3;
    size_t row0 = (size_t)blockIdx.x * ROWS;

    uint32_t base = (uint32_t)__cvta_generic_to_shared(smem);
    uint32_t hnb = base + OFF_HN;
    uint32_t tb  = base + OFF_T;
    uint32_t wb  = base + OFF_WB;

    // A ldsm: rows wm*16 + (lane&15), khalf = lane>>4
    uint32_t aoff = (uint32_t)(((wm * 16 + (lane & 15)) * TLW + (lane >> 4) * 4) * 4);
    // B ldsm: n-warp wn covers jp = wn*4 .. wn*4+3
    uint32_t boff = (uint32_t)(wn * 4 * 512 + lane * 16);

    // prefetch sub-chunk 0 (16KB, 4 cp16/thread)
    {
        uint32_t d = wb + tid * 16;
        const char* s = (const char*)g_wpack + tid * 16;
        cp16(d, s); cp16(d + 4096, s + 4096);
        cp16(d + 8192, s + 8192); cp16(d + 12288, s + 12288);
        asm volatile("cp.async.commit_group;");
    }

    // ================= input projection =================
    {
        float* s_x  = (float*)(smem + OFF_HN);   // [64][36]
        float* s_pw = (float*)(smem + OFF_T);    // [32][132]
        for (int i = tid; i < 1024; i += THREADS) {
            int r = i >> 5, c4 = i & 31;
            *(float4*)&s_pw[r * LDH + c4 * 4] = *(const float4*)(pw + r * DIM + c4 * 4);
        }
        for (int i = tid; i < 512; i += THREADS) {
            int r = i >> 3, c4 = i & 7;
            *(float4*)&s_x[r * 36 + c4 * 4] = *(const float4*)(xg + (row0 + r) * FIN + c4 * 4);
        }
        __syncthreads();
        int pr = tid >> 2, qt = tid & 3;
        int colb = qt * 32;
        float4 acc[8];
#pragma unroll
        for (int c4 = 0; c4 < 8; c4++) {
            int col = colb + c4 * 4;
            float4 a = *(const float4*)(pb + col);
            float4 po = *(const float4*)(pos + col);
            acc[c4].x = a.x + po.x; acc[c4].y = a.y + po.y;
            acc[c4].z = a.z + po.z; acc[c4].w = a.w + po.w;
        }
#pragma unroll 8
        for (int k = 0; k < FIN; k++) {
            float a = s_x[pr * 36 + k];
#pragma unroll
            for (int c4 = 0; c4 < 8; c4++) {
                float4 w = *(const float4*)&s_pw[k * LDH + colb + c4 * 4];
                acc[c4].x += a * w.x; acc[c4].y += a * w.y;
                acc[c4].z += a * w.z; acc[c4].w += a * w.w;
            }
        }
        __syncthreads();
#pragma unroll
        for (int c4 = 0; c4 < 8; c4++)
            *(float4*)&s_h[pr * LDH + colb + c4 * 4] = acc[c4];
        __syncthreads();
    }

    // ============================ 8 expert slots ============================
    for (int slot = 0; slot < NL * KSEL; slot++) {
        int blk = g_sel[slot];
        size_t bo = (size_t)((slot >> 1) * NB + blk);
        const float* LS = ln_s + bo * DIM;
        const float* LB = ln_b + bo * DIM;
        s_b1[tid] = __ldg(b1g + bo * HID + tid);
        if (tid < DIM) s_b2[tid] = g_b2f[slot][tid];

        // ---- LayerNorm -> hn32 (8 warps x 8 rows) ----
        {
            float4 ls4 = *(const float4*)(LS + lane * 4);
            float4 lb4 = *(const float4*)(LB + lane * 4);
#pragma unroll
            for (int rr = 0; rr < 8; rr++) {
                int r = wid * 8 + rr;
                float4 v = *(const float4*)&s_h[r * LDH + lane * 4];
                float s = v.x + v.y + v.z + v.w;
                float q = v.x * v.x + v.y * v.y + v.z * v.z + v.w * v.w;
#pragma unroll
                for (int o = 16; o > 0; o >>= 1) {
                    s += __shfl_xor_sync(0xffffffffu, s, o);
                    q += __shfl_xor_sync(0xffffffffu, q, o);
                }
                float mu = s * (1.0f / DIM);
                float rstd = rsqrtf(q * (1.0f / DIM) - mu * mu + 1e-5f);
                uint2 pk;
                pk.x = pkf2((v.x - mu) * rstd * ls4.x + lb4.x,
                            (v.y - mu) * rstd * ls4.y + lb4.y);
                pk.y = pkf2((v.z - mu) * rstd * ls4.z + lb4.z,
                            (v.w - mu) * rstd * ls4.w + lb4.w);
                *(uint2*)&hn32[r * TLW + lane * 2] = pk;
            }
        }

        float zacc[8][4];
#pragma unroll
        for (int j = 0; j < 8; j++)
#pragma unroll
            for (int e = 0; e < 4; e++) zacc[j][e] = 0.0f;

        for (int half = 0; half < 2; half++) {
#pragma unroll
            for (int g2 = 0; g2 < 2; g2++) {
                int ph = half * 2 + g2;
                uint32_t Ab = (g2 ? tb : hnb) + aoff;

                float c1[8][4];
                if (!g2) {
#pragma unroll
                    for (int j = 0; j < 8; j++)
#pragma unroll
                        for (int e = 0; e < 4; e++) c1[j][e] = 0.0f;
                }
                float (*acc)[4] = g2 ? zacc : c1;

                // two 16KB sub-chunks per phase (ks 0..3, ks 4..7)
#pragma unroll
                for (int sc2 = 0; sc2 < 2; sc2++) {
                    int sq = (slot * 4 + ph) * 2 + sc2;
                    asm volatile("cp.async.wait_group 0;" ::: "memory");
                    __syncthreads();
                    {
                        int nq = sq + 1;
                        if (nq < 64) {
                            uint32_t d = wb + (nq & 1) * 16384 + tid * 16;
                            const char* s = (const char*)g_wpack + (size_t)nq * 16384 + tid * 16;
                            cp16(d, s); cp16(d + 4096, s + 4096);
                            cp16(d + 8192, s + 8192); cp16(d + 12288, s + 12288);
                        }
                        asm volatile("cp.async.commit_group;");
                    }
                    uint32_t sb = wb + (sq & 1) * 16384;
#pragma unroll
                    for (int ksl = 0; ksl < 4; ksl++) {
                        int ks = sc2 * 4 + ksl;
                        uint32_t bu0[4], bu1[4], bu2[4], bu3[4];
                        ldsm4(bu0, sb + boff + ksl * 4096);
                        ldsm4(bu1, sb + boff + ksl * 4096 + 512);
                        ldsm4(bu2, sb + boff + ksl * 4096 + 1024);
                        ldsm4(bu3, sb + boff + ksl * 4096 + 1536);
                        uint32_t a[4];
                        ldsm4(a, Ab + ks * 32);
                        mma_fp16(acc[0], a[0], a[1], a[2], a[3], bu0[0], bu0[1]);
                        mma_fp16(acc[1], a[0], a[1], a[2], a[3], bu0[2], bu0[3]);
                        mma_fp16(acc[2], a[0], a[1], a[2], a[3], bu1[0], bu1[1]);
                        mma_fp16(acc[3], a[0], a[1], a[2], a[3], bu1[2], bu1[3]);
                        mma_fp16(acc[4], a[0], a[1], a[2], a[3], bu2[0], bu2[1]);
                        mma_fp16(acc[5], a[0], a[1], a[2], a[3], bu2[2], bu2[3]);
                        mma_fp16(acc[6], a[0], a[1], a[2], a[3], bu3[0], bu3[1]);
                        mma_fp16(acc[7], a[0], a[1], a[2], a[3], bu3[2], bu3[3]);
                    }
                }

                if (!g2) {
                    // ---- +b1, fast GELU -> t32 (128 cols of this half) ----
#pragma unroll
                    for (int j = 0; j < 8; j++) {
                        int colp = wn * 64 + j * 8 + 2 * tg;
                        float bb0 = s_b1[half * 128 + colp];
                        float bb1 = s_b1[half * 128 + colp + 1];
                        int r = wm * 16 + g;
                        int cw = wn * 32 + j * 4 + tg;
                        t32[r * TLW + cw] =
                            pkf2(gelu_fast(c1[j][0] + bb0), gelu_fast(c1[j][1] + bb1));
                        t32[(r + 8) * TLW + cw] =
                            pkf2(gelu_fast(c1[j][2] + bb0), gelu_fast(c1[j][3] + bb1));
                    }
                }
            }
        }

        // ---- residual: h += zacc + b2f ----
        __syncthreads();
#pragma unroll
        for (int j = 0; j < 8; j++) {
            int col = wn * 64 + j * 8 + 2 * tg;
            float bb0 = s_b2[col], bb1 = s_b2[col + 1];
            int r = wm * 16 + g;
            float2 hv = *(float2*)&s_h[r * LDH + col];
            hv.x += zacc[j][0] + bb0;
            hv.y += zacc[j][1] + bb1;
            *(float2*)&s_h[r * LDH + col] = hv;
            float2 hw = *(float2*)&s_h[(r + 8) * LDH + col];
            hw.x += zacc[j][2] + bb0;
            hw.y += zacc[j][3] + bb1;
            *(float2*)&s_h[(r + 8) * LDH + col] = hw;
        }
        __syncthreads();
    }

    // ============================ classifier + emit ============================
    {
        float2 cw[4];
#pragma unroll
        for (int ci = 0; ci < 4; ci++)
            cw[ci] = *(const float2*)(cls_w + (lane * 4 + ci) * 2);
        float cb0 = cls_b[0], cb1 = cls_b[1];
#pragma unroll
        for (int rr = 0; rr < 8; rr++) {
            int r = wid * 8 + rr;
            float4 v = *(const float4*)&s_h[r * LDH + lane * 4];
            float a0 = v.x * cw[0].x + v.y * cw[1].x + v.z * cw[2].x + v.w * cw[3].x;
            float a1 = v.x * cw[0].y + v.y * cw[1].y + v.z * cw[2].y + v.w * cw[3].y;
#pragma unroll
            for (int o = 16; o > 0; o >>= 1) {
                a0 += __shfl_xor_sync(0xffffffffu, a0, o);
                a1 += __shfl_xor_sync(0xffffffffu, a1, o);
            }
            if (lane == 0) {
                size_t row = row0 + r;
                out[row * 2]     = a0 + cb0;
                out[row * 2 + 1] = a1 + cb1;
            }
        }
        for (int i = tid; i < ROWS * 32; i += THREADS) {
            int r = i >> 5, c = (i & 31) * 4;
            *(float4*)&out[(size_t)B_TOTAL * 2 + (row0 + r) * DIM + c] =
                *(const float4*)&s_h[r * LDH + c];
        }
    }
}

// ---------------------------------------------------------------------------
extern "C" void kernel_launch(void* const* d_in, const int* in_sizes, int n_in,
                              void* d_out, int out_size) {
    const float* x      = (const float*)d_in[0];
    const float* proj_w = (const float*)d_in[1];
    const float* proj_b = (const float*)d_in[2];
    const float* pos    = (const float*)d_in[3];
    const float* sel_w  = (const float*)d_in[4];
    const float* sel_b  = (const float*)d_in[5];
    const float* ln_s   = (const float*)d_in[6];
    const float* ln_b   = (const float*)d_in[7];
    const float* w1     = (const float*)d_in[8];
    const float* b1     = (const float*)d_in[9];
    const float* w2     = (const float*)d_in[10];
    const float* b2     = (const float*)d_in[11];
    const float* gate   = (const float*)d_in[12];
    const float* cls_w  = (const float*)d_in[13];
    const float* cls_b  = (const float*)d_in[14];
    const float* tf     = (const float*)d_in[15];
    float* out = (float*)d_out;

    const int pilot_smem = 28832 * 4;
    cudaFuncSetAttribute(pilot_kernel, cudaFuncAttributeMaxDynamicSharedMemorySize, pilot_smem);
    cudaFuncSetAttribute(fused_kernel, cudaFuncAttributeMaxDynamicSharedMemorySize, SMEM_TOT);

    pilot_kernel<<<1, 1024, pilot_smem>>>(x, proj_w, proj_b, pos, sel_w, sel_b, ln_s, ln_b,
                                          w1, b1, w2, b2, gate, tf);
    repack_kernel<<<32, 256>>>(w1, w2);
    fused_kernel<<<B_TOTAL / ROWS, THREADS, SMEM_TOT>>>(
        x, proj_w, proj_b, pos, b1, ln_s, ln_b, cls_w, cls_b, out);
}

// round 15
// speedup vs baseline: 5.5607x; 1.0272x over previous
#include <cuda_runtime.h>
#include <cuda_fp16.h>
#include <math.h>
#include <stdint.h>

#define B_TOTAL 131072
#define DIM     128
#define HID     256
#define NB      8
#define NL      4
#define KSEL    2
#define FIN     32
#define ROWS    128
#define LDH     132          // s_h float stride
#define TLW     68           // fp16 tile stride in 32-bit words
#define THREADS 512

typedef unsigned long long u64;

__device__ int   g_sel[NL * KSEL];
__device__ float g_gfac[NL * KSEL][DIM];
__device__ float g_b2f[NL * KSEL][DIM];     // 0.5 * b2 * gfac
// 32 chunks x 32KB: [ks(8)][jp(8)][tile4][8n][8k] fp16 tiles for ldmatrix
__device__ __align__(256) uint4 g_wpack[65536];

__device__ __forceinline__ float sigm(float x) { return 1.0f / (1.0f + expf(-x)); }
__device__ __forceinline__ float gelu_exact(float x) {
    return 0.5f * x * (1.0f + erff(x * 0.70710678118654752440f));
}
// Branchless GELU (A&S 7.1.26, abs err 1.5e-7; validated R9-R11)
__device__ __forceinline__ float gelu_fast(float x) {
    float u = fabsf(x) * 0.70710678118654752440f;
    float t = __fdividef(1.0f, fmaf(0.3275911f, u, 1.0f));
    float p = t * fmaf(t, fmaf(t, fmaf(t, fmaf(t, 1.061405429f, -1.453152027f),
                                       1.421413741f), -0.284496736f), 0.254829592f);
    float erfc_abs = p * __expf(-u * u);
    float er = copysignf(1.0f - erfc_abs, x);
    return 0.5f * x * (1.0f + er);
}
__device__ __forceinline__ uint32_t pkh2(float x, float y) {
    return (uint32_t)__half_as_ushort(__float2half_rn(x))
         | ((uint32_t)__half_as_ushort(__float2half_rn(y)) << 16);
}
__device__ __forceinline__ uint32_t pkf2(float lo, float hi) {
    uint32_t r;
    asm("cvt.rn.f16x2.f32 %0, %1, %2;" : "=r"(r) : "f"(hi), "f"(lo));
    return r;
}
__device__ __forceinline__ void cp16(uint32_t d, const void* s) {
    asm volatile("cp.async.cg.shared.global [%0], [%1], 16;" :: "r"(d), "l"(s));
}
__device__ __forceinline__ void mma_fp16(float c[4], uint32_t a0, uint32_t a1,
                                         uint32_t a2, uint32_t a3,
                                         uint32_t b0, uint32_t b1) {
    asm volatile("mma.sync.aligned.m16n8k16.row.col.f32.f16.f16.f32 "
        "{%0,%1,%2,%3},{%4,%5,%6,%7},{%8,%9},{%0,%1,%2,%3};"
        : "+f"(c[0]), "+f"(c[1]), "+f"(c[2]), "+f"(c[3])
        : "r"(a0), "r"(a1), "r"(a2), "r"(a3), "r"(b0), "r"(b1));
}
__device__ __forceinline__ void ldsm4(uint32_t r[4], uint32_t addr) {
    asm volatile("ldmatrix.sync.aligned.m8n8.x4.shared.b16 {%0,%1,%2,%3}, [%4];"
        : "=r"(r[0]), "=r"(r[1]), "=r"(r[2]), "=r"(r[3]) : "r"(addr));
}

// ---------------------------------------------------------------------------
// Pilot: sample-0 trajectory; params prefetched; GEMVs via float4 (LDG.128)
// ---------------------------------------------------------------------------
__global__ void __launch_bounds__(1024, 1)
pilot_kernel(const float* __restrict__ x, const float* __restrict__ pw,
             const float* __restrict__ pb, const float* __restrict__ pos,
             const float* __restrict__ sel_w, const float* __restrict__ sel_b,
             const float* __restrict__ ln_s, const float* __restrict__ ln_b,
             const float* __restrict__ w1, const float* __restrict__ b1,
             const float* __restrict__ w2, const float* __restrict__ b2,
             const float* __restrict__ gate, const float* __restrict__ tf) {
    extern __shared__ float ps[];
    float* s_selw = ps;             // 4096
    float* s_lns  = ps + 4096;      // 4096
    float* s_lnb  = ps + 8192;      // 4096
    float* s_b1a  = ps + 12288;     // 8192
    float* s_b2a  = ps + 20480;     // 4096
    float* s_gate = ps + 24576;     // 4096
    float* s_tf   = ps + 28672;     // 128
    float* s_selb = ps + 28800;     // 32

    __shared__ float h0[DIM], hn[DIM], tbuf[HID], fbuf[DIM];
    __shared__ float partf[4096];   // [16][256] for GEMV1, [32][128] for GEMV2
    __shared__ float redA[64], redB[64];
    __shared__ float sc[NB];
    __shared__ int   seli[KSEL];
    __shared__ float s_mu, s_rstd;
    int tid = threadIdx.x, lane = tid & 31, wid = tid >> 5;

    // bulk prefetch of all small parameters
    {
        ((float4*)s_selw)[tid & 1023] = ((const float4*)sel_w)[tid & 1023];
        ((float4*)s_lns)[tid & 1023]  = ((const float4*)ln_s)[tid & 1023];
        ((float4*)s_lnb)[tid & 1023]  = ((const float4*)ln_b)[tid & 1023];
        ((float4*)s_b1a)[tid]         = ((const float4*)b1)[tid];
        ((float4*)s_b1a)[tid + 1024]  = ((const float4*)b1)[tid + 1024];
        ((float4*)s_b2a)[tid & 1023]  = ((const float4*)b2)[tid & 1023];
        ((float4*)s_gate)[tid & 1023] = ((const float4*)gate)[tid & 1023];
        if (tid < 32) ((float4*)s_tf)[tid] = ((const float4*)tf)[tid];
        else if (tid < 40) ((float4*)s_selb)[tid - 32] = ((const float4*)sel_b)[tid - 32];
    }

    if (tid < DIM) {
        float acc = pb[tid] + pos[tid];
#pragma unroll
        for (int k = 0; k < FIN; k++) acc += x[k] * pw[k * DIM + tid];
        h0[tid] = acc;
    }
    __syncthreads();

    for (int l = 0; l < NL; l++) {
        {
            int b = tid >> 7, d = tid & 127;
            float pv = h0[d] * s_selw[(l * DIM + d) * NB + b];
#pragma unroll
            for (int o = 16; o > 0; o >>= 1) pv += __shfl_xor_sync(0xffffffffu, pv, o);
            if (lane == 0) partf[wid] = pv;
        }
        __syncthreads();
        if (tid < NB) {
            float s = partf[tid * 4] + partf[tid * 4 + 1]
                    + partf[tid * 4 + 2] + partf[tid * 4 + 3];
            sc[tid] = sigm(s + s_selb[l * NB + tid]) * 0.6f + 0.2f;
        }
        __syncthreads();
        if (tid == 0) {
            int i0 = 0; float v0 = -1e30f;
            for (int j = 0; j < NB; j++) if (sc[j] > v0) { v0 = sc[j]; i0 = j; }
            int i1 = -1; float v1 = -1e30f;
            for (int j = 0; j < NB; j++) { if (j == i0) continue; if (sc[j] > v1) { v1 = sc[j]; i1 = j; } }
            seli[0] = i0; seli[1] = i1;
            g_sel[l * KSEL + 0] = i0; g_sel[l * KSEL + 1] = i1;
        }
        __syncthreads();

        for (int k = 0; k < KSEL; k++) {
            int i = seli[k];
            int bo = l * NB + i;
            if (tid < DIM) {
                float fv = 1.0f + sigm(s_gate[bo * DIM + tid]) * s_tf[tid];
                fbuf[tid] = fv;
                g_gfac[l * KSEL + k][tid] = fv;
                g_b2f[l * KSEL + k][tid] = 0.5f * s_b2a[bo * DIM + tid] * fv;
            }
            if (tid < 64) {
                float a = h0[tid], b = h0[tid + 64];
                redA[tid] = a + b; redB[tid] = a * a + b * b;
            }
            __syncthreads();
            if (tid == 0) {
                float s = 0.f, q = 0.f;
                for (int j = 0; j < 64; j++) { s += redA[j]; q += redB[j]; }
                float mu = s * (1.0f / DIM);
                s_mu = mu;
                s_rstd = rsqrtf(q * (1.0f / DIM) - mu * mu + 1e-5f);
            }
            __syncthreads();
            if (tid < DIM)
                hn[tid] = (h0[tid] - s_mu) * s_rstd * s_lns[bo * DIM + tid] + s_lnb[bo * DIM + tid];
            __syncthreads();
            // GEMV1: 16 k-segs x 8, float4 loads (LDG.128)
            {
                int c4 = tid & 63, seg = tid >> 6, k0 = seg * 8;
                const float* W1 = w1 + (size_t)bo * DIM * HID;
                float4 acc = make_float4(0.f, 0.f, 0.f, 0.f);
#pragma unroll
                for (int kk = 0; kk < 8; kk++) {
                    float a = hn[k0 + kk];
                    float4 w = __ldg((const float4*)&W1[(size_t)(k0 + kk) * HID + c4 * 4]);
                    acc.x += a * w.x; acc.y += a * w.y;
                    acc.z += a * w.z; acc.w += a * w.w;
                }
                *(float4*)&partf[seg * 256 + c4 * 4] = acc;
            }
            __syncthreads();
            if (tid < HID) {
                float s = s_b1a[bo * HID + tid];
#pragma unroll
                for (int sg = 0; sg < 16; sg++) s += partf[sg * 256 + tid];
                tbuf[tid] = gelu_exact(s);
            }
            __syncthreads();
            // GEMV2: 32 k-segs x 8, float4 loads
            {
                int c4 = tid & 31, seg = tid >> 5, k0 = seg * 8;
                const float* W2 = w2 + (size_t)bo * HID * DIM;
                float4 acc = make_float4(0.f, 0.f, 0.f, 0.f);
#pragma unroll
                for (int kk = 0; kk < 8; kk++) {
                    float a = tbuf[k0 + kk];
                    float4 w = __ldg((const float4*)&W2[(size_t)(k0 + kk) * DIM + c4 * 4]);
                    acc.x += a * w.x; acc.y += a * w.y;
                    acc.z += a * w.z; acc.w += a * w.w;
                }
                *(float4*)&partf[seg * 128 + c4 * 4] = acc;
            }
            __syncthreads();
            if (tid < DIM) {
                float z = s_b2a[bo * DIM + tid];
#pragma unroll
                for (int sg = 0; sg < 32; sg++) z += partf[sg * 128 + tid];
                h0[tid] += 0.5f * z * fbuf[tid];
            }
            __syncthreads();
        }
    }
}

// ---------------------------------------------------------------------------
// Repack (R11 layout, 64 blocks: each handles half a chunk)
// ---------------------------------------------------------------------------
__global__ void repack_kernel(const float* __restrict__ w1g, const float* __restrict__ w2g) {
    int q = blockIdx.x >> 1;            // 0..31
    int e2base = (blockIdx.x & 1) * 4096;
    int slot = q >> 2, phase = q & 3;
    int half = phase >> 1;
    bool isG2 = phase & 1;
    int blk = g_sel[slot];
    size_t bo = (size_t)((slot >> 1) * NB + blk);
    const float* W = isG2 ? (w2g + bo * HID * DIM) : (w1g + bo * DIM * HID);
    int ld = isG2 ? DIM : HID;
    uint32_t* dst = (uint32_t*)g_wpack + (size_t)q * 8192;
    for (int e2 = e2base + threadIdx.x; e2 < e2base + 4096; e2 += 256) {
        int k2 = e2 & 3, nl = (e2 >> 2) & 7, t = (e2 >> 5) & 3;
        int jp = (e2 >> 7) & 7, ks = e2 >> 10;
        int j = jp * 2 + (t >> 1), kh = t & 1, kl = k2 * 2;
        int k, n;
        float scl = 1.0f;
        if (!isG2) { k = ks * 16 + kh * 8 + kl; n = half * 128 + j * 8 + nl; }
        else       { k = half * 128 + ks * 16 + kh * 8 + kl; n = j * 8 + nl;
                     scl = 0.5f * g_gfac[slot][n]; }
        dst[e2] = pkh2(__ldg(&W[(size_t)k * ld + n]) * scl,
                       __ldg(&W[(size_t)(k + 1) * ld + n]) * scl);
    }
}

// ---------------------------------------------------------------------------
// SMEM byte offsets (R11 layout)
// ---------------------------------------------------------------------------
#define OFF_H    0                    // 128*132*4 = 67584
#define OFF_HN   67584                // 128*68*4  = 34816
#define OFF_T    102400               // 128*68*4  = 34816
#define OFF_WB   137216               // 2 x 32768 = 65536
#define OFF_B1   202752               // 1024
#define OFF_B2   203776               // 512
#define SMEM_TOT 204288

// ---------------------------------------------------------------------------
// Fused (R11-proven): proj -> 8 expert blocks (fp16 mma + ldmatrix) -> head
// ---------------------------------------------------------------------------
__global__ void __launch_bounds__(THREADS, 1)
fused_kernel(const float* __restrict__ xg, const float* __restrict__ pw,
             const float* __restrict__ pb, const float* __restrict__ pos,
             const float* __restrict__ b1g,
             const float* __restrict__ ln_s, const float* __restrict__ ln_b,
             const float* __restrict__ cls_w, const float* __restrict__ cls_b,
             float* __restrict__ out) {
    extern __shared__ char smem[];
    float*    s_h  = (float*)(smem + OFF_H);
    uint32_t* hn32 = (uint32_t*)(smem + OFF_HN);
    uint32_t* t32  = (uint32_t*)(smem + OFF_T);
    float*    s_b1 = (float*)(smem + OFF_B1);
    float*    s_b2 = (float*)(smem + OFF_B2);

    int tid = threadIdx.x, lane = tid & 31, wid = tid >> 5;
    int wm = wid >> 2, wn = wid & 3;          // 4 x 4 warp grid
    int g = lane >> 2, tg = lane & 3;
    size_t row0 = (size_t)blockIdx.x * ROWS;

    uint32_t base = (uint32_t)__cvta_generic_to_shared(smem);
    uint32_t hnb = base + OFF_HN;
    uint32_t tb  = base + OFF_T;
    uint32_t wb  = base + OFF_WB;

    uint32_t aoff = (uint32_t)(((wm * 32 + (lane & 15)) * TLW + (lane >> 4) * 4) * 4);
    uint32_t boff = (uint32_t)((wn * 2 * 128 + lane * 4) * 4);

    // prefetch chunk 0 (overlaps projection)
    {
        uint32_t d = wb + tid * 16;
        const char* s = (const char*)g_wpack + tid * 16;
        cp16(d, s); cp16(d + 8192, s + 8192);
        cp16(d + 16384, s + 16384); cp16(d + 24576, s + 24576);
        asm volatile("cp.async.commit_group;");
    }

    // ================= input projection =================
    {
        float* s_x  = (float*)(smem + OFF_HN);   // [128][36]
        float* s_pw = (float*)(smem + OFF_T);    // [32][132]
        for (int i = tid; i < 1024; i += THREADS) {
            int r = i >> 5, c4 = i & 31;
            *(float4*)&s_pw[r * LDH + c4 * 4] = *(const float4*)(pw + r * DIM + c4 * 4);
        }
        for (int i = tid; i < 1024; i += THREADS) {
            int r = i >> 3, c4 = i & 7;
            *(float4*)&s_x[r * 36 + c4 * 4] = *(const float4*)(xg + (row0 + r) * FIN + c4 * 4);
        }
        __syncthreads();
        int pr = tid >> 2, qt = tid & 3;
        int colb = qt * 32;
        float4 acc[8];
#pragma unroll
        for (int c4 = 0; c4 < 8; c4++) {
            int col = colb + c4 * 4;
            float4 a = *(const float4*)(pb + col);
            float4 po = *(const float4*)(pos + col);
            acc[c4].x = a.x + po.x; acc[c4].y = a.y + po.y;
            acc[c4].z = a.z + po.z; acc[c4].w = a.w + po.w;
        }
#pragma unroll 8
        for (int k = 0; k < FIN; k++) {
            float a = s_x[pr * 36 + k];
#pragma unroll
            for (int c4 = 0; c4 < 8; c4++) {
                float4 w = *(const float4*)&s_pw[k * LDH + colb + c4 * 4];
                acc[c4].x += a * w.x; acc[c4].y += a * w.y;
                acc[c4].z += a * w.z; acc[c4].w += a * w.w;
            }
        }
        __syncthreads();
#pragma unroll
        for (int c4 = 0; c4 < 8; c4++)
            *(float4*)&s_h[pr * LDH + colb + c4 * 4] = acc[c4];
        __syncthreads();
    }

    // ============================ 8 expert slots ============================
    for (int slot = 0; slot < NL * KSEL; slot++) {
        int blk = g_sel[slot];
        size_t bo = (size_t)((slot >> 1) * NB + blk);
        const float* LS = ln_s + bo * DIM;
        const float* LB = ln_b + bo * DIM;
        if (tid < HID) s_b1[tid] = __ldg(b1g + bo * HID + tid);
        else if (tid < HID + DIM) s_b2[tid - HID] = g_b2f[slot][tid - HID];

        // ---- LayerNorm -> hn32 ----
        {
            float4 ls4 = *(const float4*)(LS + lane * 4);
            float4 lb4 = *(const float4*)(LB + lane * 4);
#pragma unroll
            for (int rr = 0; rr < 8; rr++) {
                int r = wid * 8 + rr;
                float4 v = *(const float4*)&s_h[r * LDH + lane * 4];
                float s = v.x + v.y + v.z + v.w;
                float q = v.x * v.x + v.y * v.y + v.z * v.z + v.w * v.w;
#pragma unroll
                for (int o = 16; o > 0; o >>= 1) {
                    s += __shfl_xor_sync(0xffffffffu, s, o);
                    q += __shfl_xor_sync(0xffffffffu, q, o);
                }
                float mu = s * (1.0f / DIM);
                float rstd = rsqrtf(q * (1.0f / DIM) - mu * mu + 1e-5f);
                uint2 pk;
                pk.x = pkf2((v.x - mu) * rstd * ls4.x + lb4.x,
                            (v.y - mu) * rstd * ls4.y + lb4.y);
                pk.y = pkf2((v.z - mu) * rstd * ls4.z + lb4.z,
                            (v.w - mu) * rstd * ls4.w + lb4.w);
                *(uint2*)&hn32[r * TLW + lane * 2] = pk;
            }
        }

        float zacc[2][4][4];
#pragma unroll
        for (int mt = 0; mt < 2; mt++)
#pragma unroll
            for (int j = 0; j < 4; j++)
#pragma unroll
                for (int e = 0; e < 4; e++) zacc[mt][j][e] = 0.0f;

        for (int half = 0; half < 2; half++) {
#pragma unroll
            for (int g2 = 0; g2 < 2; g2++) {
                int q = slot * 4 + half * 2 + g2;
                asm volatile("cp.async.wait_group 0;" ::: "memory");
                __syncthreads();
                {
                    int nq = q + 1;
                    if (nq < 32) {
                        uint32_t d = wb + (nq & 1) * 32768 + tid * 16;
                        const char* s = (const char*)g_wpack + (size_t)nq * 32768 + tid * 16;
                        cp16(d, s); cp16(d + 8192, s + 8192);
                        cp16(d + 16384, s + 16384); cp16(d + 24576, s + 24576);
                    }
                    asm volatile("cp.async.commit_group;");
                }
                uint32_t wbc = wb + (q & 1) * 32768;
                uint32_t Ab = (g2 ? tb : hnb) + aoff;

                float c1[2][4][4];
                if (!g2) {
#pragma unroll
                    for (int mt = 0; mt < 2; mt++)
#pragma unroll
                        for (int j = 0; j < 4; j++)
#pragma unroll
                            for (int e = 0; e < 4; e++) c1[mt][j][e] = 0.0f;
                }
                float (*acc)[4][4] = g2 ? zacc : c1;

#pragma unroll
                for (int ks = 0; ks < 8; ks++) {
                    uint32_t b0[4], b1f[4];
                    ldsm4(b0,  wbc + boff + ks * 4096);
                    ldsm4(b1f, wbc + boff + ks * 4096 + 512);
                    uint32_t a0[4], a1[4];
                    ldsm4(a0, Ab + ks * 32);
                    ldsm4(a1, Ab + ks * 32 + 16 * TLW * 4);
#pragma unroll
                    for (int j = 0; j < 4; j++) {
                        uint32_t fb0 = (j < 2) ? b0[(j & 1) * 2]     : b1f[(j & 1) * 2];
                        uint32_t fb1 = (j < 2) ? b0[(j & 1) * 2 + 1] : b1f[(j & 1) * 2 + 1];
                        mma_fp16(acc[0][j], a0[0], a0[1], a0[2], a0[3], fb0, fb1);
                        mma_fp16(acc[1][j], a1[0], a1[1], a1[2], a1[3], fb0, fb1);
                    }
                }

                if (!g2) {
                    // ---- +b1, fast GELU -> t32 ----
#pragma unroll
                    for (int mt = 0; mt < 2; mt++)
#pragma unroll
                        for (int j = 0; j < 4; j++) {
                            int colp = wn * 32 + j * 8 + 2 * tg;
                            float bb0 = s_b1[half * 128 + colp];
                            float bb1 = s_b1[half * 128 + colp + 1];
                            int r = wm * 32 + mt * 16 + g;
                            int cw = wn * 16 + j * 4 + tg;
                            t32[r * TLW + cw] =
                                pkf2(gelu_fast(c1[mt][j][0] + bb0), gelu_fast(c1[mt][j][1] + bb1));
                            t32[(r + 8) * TLW + cw] =
                                pkf2(gelu_fast(c1[mt][j][2] + bb0), gelu_fast(c1[mt][j][3] + bb1));
                        }
                }
            }
        }

        // ---- residual: h += zacc + b2f (pre-barrier removed: s_h untouched by ph3) ----
#pragma unroll
        for (int mt = 0; mt < 2; mt++)
#pragma unroll
            for (int j = 0; j < 4; j++) {
                int col = wn * 32 + j * 8 + 2 * tg;
                float bb0 = s_b2[col], bb1 = s_b2[col + 1];
                int r = wm * 32 + mt * 16 + g;
                float2 hv = *(float2*)&s_h[r * LDH + col];
                hv.x += zacc[mt][j][0] + bb0;
                hv.y += zacc[mt][j][1] + bb1;
                *(float2*)&s_h[r * LDH + col] = hv;
                float2 hw = *(float2*)&s_h[(r + 8) * LDH + col];
                hw.x += zacc[mt][j][2] + bb0;
                hw.y += zacc[mt][j][3] + bb1;
                *(float2*)&s_h[(r + 8) * LDH + col] = hw;
            }
        __syncthreads();
    }

    // ============================ classifier + emit ============================
    {
        float2 cw[4];
#pragma unroll
        for (int ci = 0; ci < 4; ci++)
            cw[ci] = *(const float2*)(cls_w + (lane * 4 + ci) * 2);
        float cb0 = cls_b[0], cb1 = cls_b[1];
#pragma unroll
        for (int rr = 0; rr < 8; rr++) {
            int r = wid * 8 + rr;
            float4 v = *(const float4*)&s_h[r * LDH + lane * 4];
            float a0 = v.x * cw[0].x + v.y * cw[1].x + v.z * cw[2].x + v.w * cw[3].x;
            float a1 = v.x * cw[0].y + v.y * cw[1].y + v.z * cw[2].y + v.w * cw[3].y;
#pragma unroll
            for (int o = 16; o > 0; o >>= 1) {
                a0 += __shfl_xor_sync(0xffffffffu, a0, o);
                a1 += __shfl_xor_sync(0xffffffffu, a1, o);
            }
            if (lane == 0) {
                size_t row = row0 + r;
                out[row * 2]     = a0 + cb0;
                out[row * 2 + 1] = a1 + cb1;
            }
        }
        for (int i = tid; i < ROWS * 32; i += THREADS) {
            int r = i >> 5, c = (i & 31) * 4;
            *(float4*)&out[(size_t)B_TOTAL * 2 + (row0 + r) * DIM + c] =
                *(const float4*)&s_h[r * LDH + c];
        }
    }
}

// ---------------------------------------------------------------------------
extern "C" void kernel_launch(void* const* d_in, const int* in_sizes, int n_in,
                              void* d_out, int out_size) {
    const float* x      = (const float*)d_in[0];
    const float* proj_w = (const float*)d_in[1];
    const float* proj_b = (const float*)d_in[2];
    const float* pos    = (const float*)d_in[3];
    const float* sel_w  = (const float*)d_in[4];
    const float* sel_b  = (const float*)d_in[5];
    const float* ln_s   = (const float*)d_in[6];
    const float* ln_b   = (const float*)d_in[7];
    const float* w1     = (const float*)d_in[8];
    const float* b1     = (const float*)d_in[9];
    const float* w2     = (const float*)d_in[10];
    const float* b2     = (const float*)d_in[11];
    const float* gate   = (const float*)d_in[12];
    const float* cls_w  = (const float*)d_in[13];
    const float* cls_b  = (const float*)d_in[14];
    const float* tf     = (const float*)d_in[15];
    float* out = (float*)d_out;

    const int pilot_smem = 28832 * 4;   // 115328 B
    cudaFuncSetAttribute(pilot_kernel, cudaFuncAttributeMaxDynamicSharedMemorySize, pilot_smem);
    cudaFuncSetAttribute(fused_kernel, cudaFuncAttributeMaxDynamicSharedMemorySize, SMEM_TOT);

    pilot_kernel<<<1, 1024, pilot_smem>>>(x, proj_w, proj_b, pos, sel_w, sel_b, ln_s, ln_b,
                                          w1, b1, w2, b2, gate, tf);
    repack_kernel<<<64, 256>>>(w1, w2);
    fused_kernel<<<B_TOTAL / ROWS, THREADS, SMEM_TOT>>>(
        x, proj_w, proj_b, pos, b1, ln_s, ln_b, cls_w, cls_b, out);
}